// round 4
// baseline (speedup 1.0000x reference)
#include <cuda_runtime.h>

#define NN 50000
#define NE 800000
#define EE (NE + NN)
#define NG 32
#define KMAX 16
#define FIN 128
#define HID 64
#define HEADS 4
#define HC 256          // HEADS*HID
#define NP1 (NN + 1)

// ---------------- scratch (static device globals; no allocation) ----------------
__device__ float    g_h1lin[NN * HC];
__device__ float    g_agg1 [NN * HC];
__device__ float    g_as1  [NN * HEADS];
__device__ float    g_ad1  [NN * HEADS];
__device__ unsigned g_m1   [NN * HEADS];
__device__ float    g_den1 [NN * HEADS];

__device__ float    g_h2lin[NN * HID];
__device__ float    g_agg2 [NN * HID];
__device__ float    g_as2  [NN];
__device__ float    g_ad2  [NN];
__device__ unsigned g_m2   [NN];
__device__ float    g_den2 [NN];

__device__ float    g_scores[NN];
__device__ float    g_stop  [NG];
__device__ int      g_ei64;      // 1 if edge_index is int64, 0 if int32
__device__ int      g_maskmode;  // 0=uint8, 1=int32, 2=float32

// ---------------- helpers ----------------
__device__ __forceinline__ unsigned fenc(float f) {
    unsigned u = __float_as_uint(f);
    return (u & 0x80000000u) ? ~u : (u | 0x80000000u);
}
__device__ __forceinline__ float fdec(unsigned u) {
    return (u & 0x80000000u) ? __uint_as_float(u & 0x7fffffffu) : __uint_as_float(~u);
}
__device__ __forceinline__ float lrelu(float a) { return a > 0.f ? a : 0.2f * a; }

__device__ __forceinline__ float warp_sum(float v) {
#pragma unroll
    for (int o = 16; o; o >>= 1) v += __shfl_xor_sync(0xffffffffu, v, o);
    return v;
}

// Edge fetch robust to int32 vs int64 edge_index storage.
__device__ __forceinline__ void load_edge(const int* __restrict__ ei, int e, int& s, int& d) {
    if (e >= NE) { s = d = e - NE; return; }
    if (g_ei64) {                       // int64 little-endian: low word at 2*idx
        s = ei[2 * e];
        d = ei[2 * (NE + e)];
    } else {
        s = ei[e];
        d = ei[NE + e];
    }
}

// detect int64 edge_index: odd int32 words of int64 data are all 0 (ids < 2^31)
__global__ void detect_ei(const unsigned* __restrict__ ei) {
    unsigned o = ei[1] | ei[3] | ei[5] | ei[7] | ei[9] | ei[11] | ei[13] | ei[15];
    g_ei64 = (o == 0u) ? 1 : 0;
}

// detect masks dtype: bernoulli(0.3) values are 0/1 in some storage type.
//   float32 -> words contain 0x3F800000
//   uint8   -> words pack 4 bytes, values >1 appear (e.g. 0x00010100)
//   int32   -> all words in {0,1}
__global__ void detect_masks(const unsigned* __restrict__ m) {
    int lane = threadIdx.x;
    int f32 = 0, multi = 0;
    for (int i = lane; i < 2048; i += 32) {
        unsigned w = m[i];
        if (w == 0x3F800000u) f32 = 1;
        else if (w > 1u) multi = 1;
    }
    f32 = __any_sync(0xffffffffu, f32);
    multi = __any_sync(0xffffffffu, multi);
    if (lane == 0) g_maskmode = f32 ? 2 : (multi ? 0 : 1);
}

// ---------------- zero/init ----------------
__global__ void zero_l1() {
    int i = blockIdx.x * blockDim.x + threadIdx.x;
    int stride = gridDim.x * blockDim.x;
    for (int j = i; j < NN * HC; j += stride) g_agg1[j] = 0.f;
    for (int j = i; j < NN * HEADS; j += stride) { g_m1[j] = 0u; g_den1[j] = 0.f; }
}
__global__ void zero_l2() {
    int i = blockIdx.x * blockDim.x + threadIdx.x;
    int stride = gridDim.x * blockDim.x;
    for (int j = i; j < NN * HID; j += stride) g_agg2[j] = 0.f;
    for (int j = i; j < NN; j += stride) { g_m2[j] = 0u; g_den2[j] = 0.f; }
}

// ---------------- SGEMM: C[M,N] = A[M,K] @ B[K,N], fp32, BM=BN=64 BK=16 TM=TN=4 ----------------
__global__ void __launch_bounds__(256) sgemm64(const float* __restrict__ A,
                                               const float* __restrict__ B,
                                               float* __restrict__ C,
                                               int M, int N, int K) {
    const int BM = 64, BN = 64, BK = 16;
    __shared__ float As[BK][BM + 4];
    __shared__ float Bs[BK][BN];
    int tid = threadIdx.x;
    int bm = blockIdx.y * BM, bn = blockIdx.x * BN;
    int tx = tid & 15, ty = tid >> 4;

    int aRow = tid >> 2;          // 0..63
    int aCol = (tid & 3) * 4;     // 0,4,8,12
    int bRow = tid >> 4;          // 0..15
    int bCol = (tid & 15) * 4;    // 0..60

    float acc[4][4];
#pragma unroll
    for (int i = 0; i < 4; i++)
#pragma unroll
        for (int j = 0; j < 4; j++) acc[i][j] = 0.f;

    for (int k0 = 0; k0 < K; k0 += BK) {
        float4 av = make_float4(0.f, 0.f, 0.f, 0.f);
        if (bm + aRow < M)
            av = *(const float4*)&A[(size_t)(bm + aRow) * K + k0 + aCol];
        As[aCol + 0][aRow] = av.x;
        As[aCol + 1][aRow] = av.y;
        As[aCol + 2][aRow] = av.z;
        As[aCol + 3][aRow] = av.w;
        *(float4*)&Bs[bRow][bCol] = *(const float4*)&B[(size_t)(k0 + bRow) * N + bn + bCol];
        __syncthreads();
#pragma unroll
        for (int k = 0; k < BK; k++) {
            float4 a = *(const float4*)&As[k][ty * 4];
            float4 b = *(const float4*)&Bs[k][tx * 4];
            acc[0][0] += a.x * b.x; acc[0][1] += a.x * b.y; acc[0][2] += a.x * b.z; acc[0][3] += a.x * b.w;
            acc[1][0] += a.y * b.x; acc[1][1] += a.y * b.y; acc[1][2] += a.y * b.z; acc[1][3] += a.y * b.w;
            acc[2][0] += a.z * b.x; acc[2][1] += a.z * b.y; acc[2][2] += a.z * b.z; acc[2][3] += a.z * b.w;
            acc[3][0] += a.w * b.x; acc[3][1] += a.w * b.y; acc[3][2] += a.w * b.z; acc[3][3] += a.w * b.w;
        }
        __syncthreads();
    }
#pragma unroll
    for (int i = 0; i < 4; i++) {
        int r = bm + ty * 4 + i;
        if (r < M)
            *(float4*)&C[(size_t)r * N + bn + tx * 4] =
                make_float4(acc[i][0], acc[i][1], acc[i][2], acc[i][3]);
    }
}

// ---------------- layer 1: attention coefficients per node ----------------
__global__ void __launch_bounds__(256) prep1(const float* __restrict__ ws,
                                             const float* __restrict__ wd) {
    int w = (blockIdx.x * blockDim.x + threadIdx.x) >> 5;
    int lane = threadIdx.x & 31;
    if (w >= NN) return;
    const float4* hp = (const float4*)(g_h1lin + (size_t)w * HC + lane * 8);
    float4 v0 = hp[0], v1 = hp[1];
    const float4* sp = (const float4*)(ws + lane * 8);
    float4 s0 = sp[0], s1 = sp[1];
    const float4* dp = (const float4*)(wd + lane * 8);
    float4 d0 = dp[0], d1 = dp[1];
    float a = v0.x * s0.x + v0.y * s0.y + v0.z * s0.z + v0.w * s0.w
            + v1.x * s1.x + v1.y * s1.y + v1.z * s1.z + v1.w * s1.w;
    float b = v0.x * d0.x + v0.y * d0.y + v0.z * d0.z + v0.w * d0.w
            + v1.x * d1.x + v1.y * d1.y + v1.z * d1.z + v1.w * d1.w;
#pragma unroll
    for (int o = 4; o; o >>= 1) {
        a += __shfl_xor_sync(0xffffffffu, a, o);
        b += __shfl_xor_sync(0xffffffffu, b, o);
    }
    if ((lane & 7) == 0) {
        int h = lane >> 3;
        g_as1[(size_t)w * 4 + h] = a;
        g_ad1[(size_t)w * 4 + h] = b;
    }
}

__global__ void __launch_bounds__(256) edge_max1(const int* __restrict__ ei) {
    int e = blockIdx.x * blockDim.x + threadIdx.x;
    if (e >= EE) return;
    int s, d;
    load_edge(ei, e, s, d);
    float4 a = *(const float4*)(g_as1 + (size_t)s * 4);
    float4 b = *(const float4*)(g_ad1 + (size_t)d * 4);
    unsigned* m = g_m1 + (size_t)d * 4;
    atomicMax(m + 0, fenc(lrelu(a.x + b.x)));
    atomicMax(m + 1, fenc(lrelu(a.y + b.y)));
    atomicMax(m + 2, fenc(lrelu(a.z + b.z)));
    atomicMax(m + 3, fenc(lrelu(a.w + b.w)));
}

__global__ void __launch_bounds__(256) edge_agg1(const int* __restrict__ ei) {
    int w = (blockIdx.x * blockDim.x + threadIdx.x) >> 5;
    int lane = threadIdx.x & 31;
    if (w >= EE) return;
    int s, d;
    load_edge(ei, w, s, d);
    float ex = 0.f;
    if (lane < 4) {
        float a = lrelu(g_as1[(size_t)s * 4 + lane] + g_ad1[(size_t)d * 4 + lane]);
        ex = __expf(a - fdec(g_m1[(size_t)d * 4 + lane]));
        atomicAdd(&g_den1[(size_t)d * 4 + lane], ex);
    }
    float exh = __shfl_sync(0xffffffffu, ex, lane >> 3);  // head = lane/8
    const float4* hp = (const float4*)(g_h1lin + (size_t)s * HC + lane * 8);
    float4 v0 = hp[0], v1 = hp[1];
    float* op = g_agg1 + (size_t)d * HC + lane * 8;
    atomicAdd(op + 0, exh * v0.x);
    atomicAdd(op + 1, exh * v0.y);
    atomicAdd(op + 2, exh * v0.z);
    atomicAdd(op + 3, exh * v0.w);
    atomicAdd(op + 4, exh * v1.x);
    atomicAdd(op + 5, exh * v1.y);
    atomicAdd(op + 6, exh * v1.z);
    atomicAdd(op + 7, exh * v1.w);
}

__global__ void __launch_bounds__(256) finalize1(const float* __restrict__ b1) {
    int i = blockIdx.x * blockDim.x + threadIdx.x;
    if (i >= NN * HC) return;
    int n = i >> 8;
    int c = i & 255;
    int h = c >> 6;
    float v = g_agg1[i] / g_den1[(size_t)n * 4 + h] + b1[c];
    g_agg1[i] = v > 0.f ? v : 0.f;   // relu; h1 lives in g_agg1
}

// ---------------- layer 2 ----------------
__global__ void __launch_bounds__(256) prep2(const float* __restrict__ ws,
                                             const float* __restrict__ wd) {
    int w = (blockIdx.x * blockDim.x + threadIdx.x) >> 5;
    int lane = threadIdx.x & 31;
    if (w >= NN) return;
    float2 v = *(const float2*)(g_h2lin + (size_t)w * HID + lane * 2);
    float2 s = *(const float2*)(ws + lane * 2);
    float2 dd = *(const float2*)(wd + lane * 2);
    float a = v.x * s.x + v.y * s.y;
    float b = v.x * dd.x + v.y * dd.y;
    a = warp_sum(a);
    b = warp_sum(b);
    if (lane == 0) { g_as2[w] = a; g_ad2[w] = b; }
}

__global__ void __launch_bounds__(256) edge_max2(const int* __restrict__ ei) {
    int e = blockIdx.x * blockDim.x + threadIdx.x;
    if (e >= EE) return;
    int s, d;
    load_edge(ei, e, s, d);
    float a = lrelu(g_as2[s] + g_ad2[d]);
    atomicMax(&g_m2[d], fenc(a));
}

__global__ void __launch_bounds__(256) edge_agg2(const int* __restrict__ ei) {
    int w = (blockIdx.x * blockDim.x + threadIdx.x) >> 5;
    int lane = threadIdx.x & 31;
    if (w >= EE) return;
    int s, d;
    load_edge(ei, w, s, d);
    float ex = 0.f;
    if (lane == 0) {
        float a = lrelu(g_as2[s] + g_ad2[d]);
        ex = __expf(a - fdec(g_m2[d]));
        atomicAdd(&g_den2[d], ex);
    }
    ex = __shfl_sync(0xffffffffu, ex, 0);
    float2 v = *(const float2*)(g_h2lin + (size_t)s * HID + lane * 2);
    float* op = g_agg2 + (size_t)d * HID + lane * 2;
    atomicAdd(op + 0, ex * v.x);
    atomicAdd(op + 1, ex * v.y);
}

// finalize layer 2 + node scores (tanh(h2 @ action_w + action_b))
__global__ void __launch_bounds__(256) finalize2(const float* __restrict__ b2,
                                                 const float* __restrict__ aw,
                                                 const float* __restrict__ ab) {
    int w = (blockIdx.x * blockDim.x + threadIdx.x) >> 5;
    int lane = threadIdx.x & 31;
    if (w >= NN) return;
    int c = lane * 2;
    float den = g_den2[w];
    float2 v = *(float2*)(g_agg2 + (size_t)w * HID + c);
    v.x = v.x / den + b2[c];
    v.y = v.y / den + b2[c + 1];
    *(float2*)(g_agg2 + (size_t)w * HID + c) = v;   // h2 in place
    float acc = v.x * aw[c] + v.y * aw[c + 1];
    acc = warp_sum(acc);
    if (lane == 0) g_scores[w] = tanhf(acc + ab[0]);
}

// per-graph masked mean pooling + stop score
__global__ void context_kernel(const int* __restrict__ cn, const int* __restrict__ cc,
                               const float* __restrict__ sw, const float* __restrict__ sb) {
    int g = blockIdx.x;
    int c = threadIdx.x;   // 64 threads
    int cnt = cc[g];
    float sum = 0.f;
#pragma unroll
    for (int k = 0; k < KMAX; k++) {
        if (k < cnt) {
            int n = cn[g * KMAX + k];
            sum += g_agg2[(size_t)n * HID + c];
        }
    }
    int cm = cnt > 1 ? cnt : 1;
    float ctx = sum / (float)cm;
    __shared__ float red[64];
    red[c] = ctx * sw[c];
    __syncthreads();
    for (int o = 32; o; o >>= 1) {
        if (c < o) red[c] += red[c + o];
        __syncthreads();
    }
    if (c == 0) g_stop[g] = tanhf(red[0] + sb[0]);
}

// mask accessor: mode-dependent dtype
__device__ __forceinline__ bool get_mask(const void* masks, int mode, int g, int i) {
    if (mode == 2) return ((const float*)masks)[(size_t)g * NN + i] != 0.f;
    if (mode == 1) return ((const int*)masks)[(size_t)g * NN + i] != 0;
    return ((const unsigned char*)masks)[(size_t)g * NN + i] != 0;
}

// per-graph masked softmax over N+1
__global__ void __launch_bounds__(1024) softmax_kernel(const void* __restrict__ masks,
                                                       const int* __restrict__ cc,
                                                       float* __restrict__ out) {
    int g = blockIdx.x;
    int tid = threadIdx.x;
    int lane = tid & 31, wid = tid >> 5;
    int mode = g_maskmode;
    float* o = out + (size_t)g * NP1;
    if (cc[g] == 0) {
        for (int i = tid; i < NP1; i += 1024) o[i] = (i == NN) ? 1.f : 0.f;
        return;
    }
    __shared__ float sm[32];
    __shared__ float bc[2];

    // pass 1: max
    float mx = -3.4e38f;
    for (int i = tid; i < NN; i += 1024) {
        float s = get_mask(masks, mode, g, i) ? g_scores[i] : -1e9f;
        mx = fmaxf(mx, s);
    }
#pragma unroll
    for (int o2 = 16; o2; o2 >>= 1) mx = fmaxf(mx, __shfl_xor_sync(0xffffffffu, mx, o2));
    if (lane == 0) sm[wid] = mx;
    __syncthreads();
    if (wid == 0) {
        float v = sm[lane];
#pragma unroll
        for (int o2 = 16; o2; o2 >>= 1) v = fmaxf(v, __shfl_xor_sync(0xffffffffu, v, o2));
        if (lane == 0) bc[0] = fmaxf(v, g_stop[g]);
    }
    __syncthreads();
    mx = bc[0];

    // pass 2: sum of exp
    float sum = 0.f;
    for (int i = tid; i < NN; i += 1024) {
        float s = get_mask(masks, mode, g, i) ? g_scores[i] : -1e9f;
        sum += __expf(s - mx);
    }
    sum = warp_sum(sum);
    __syncthreads();
    if (lane == 0) sm[wid] = sum;
    __syncthreads();
    if (wid == 0) {
        float v = sm[lane];
        v = warp_sum(v);
        if (lane == 0) bc[1] = v + __expf(g_stop[g] - mx);
    }
    __syncthreads();
    float inv = 1.f / bc[1];

    // pass 3: write probs
    for (int i = tid; i < NN; i += 1024) {
        float s = get_mask(masks, mode, g, i) ? g_scores[i] : -1e9f;
        o[i] = __expf(s - mx) * inv;
    }
    if (tid == 0) o[NN] = __expf(g_stop[g] - mx) * inv;
}

// ---------------- host ----------------
extern "C" void kernel_launch(void* const* d_in, const int* in_sizes, int n_in,
                              void* d_out, int out_size) {
    const float* x    = (const float*)d_in[0];
    const int*   ei   = (const int*)d_in[1];
    const int*   cn   = (const int*)d_in[2];
    const int*   cc   = (const int*)d_in[3];
    const void*  masks = d_in[4];
    const float* W1   = (const float*)d_in[5];
    const float* as1w = (const float*)d_in[6];
    const float* ad1w = (const float*)d_in[7];
    const float* b1   = (const float*)d_in[8];
    const float* W2   = (const float*)d_in[9];
    const float* as2w = (const float*)d_in[10];
    const float* ad2w = (const float*)d_in[11];
    const float* b2   = (const float*)d_in[12];
    const float* aw   = (const float*)d_in[13];
    const float* ab   = (const float*)d_in[14];
    const float* sw   = (const float*)d_in[15];
    const float* sb   = (const float*)d_in[16];
    float* out = (float*)d_out;

    float *h1lin_p, *agg1_p, *h2lin_p;
    cudaGetSymbolAddress((void**)&h1lin_p, g_h1lin);
    cudaGetSymbolAddress((void**)&agg1_p, g_agg1);
    cudaGetSymbolAddress((void**)&h2lin_p, g_h2lin);

    detect_ei<<<1, 1>>>((const unsigned*)ei);
    detect_masks<<<1, 32>>>((const unsigned*)masks);

    // layer 1
    zero_l1<<<1024, 256>>>();
    sgemm64<<<dim3(HC / 64, (NN + 63) / 64), 256>>>(x, W1, h1lin_p, NN, HC, FIN);
    prep1<<<(NN + 7) / 8, 256>>>(as1w, ad1w);
    edge_max1<<<(EE + 255) / 256, 256>>>(ei);
    edge_agg1<<<(EE + 7) / 8, 256>>>(ei);
    finalize1<<<(NN * HC + 255) / 256, 256>>>(b1);

    // layer 2
    zero_l2<<<1024, 256>>>();
    sgemm64<<<dim3(HID / 64, (NN + 63) / 64), 256>>>(agg1_p, W2, h2lin_p, NN, HID, HC);
    prep2<<<(NN + 7) / 8, 256>>>(as2w, ad2w);
    edge_max2<<<(EE + 255) / 256, 256>>>(ei);
    edge_agg2<<<(EE + 7) / 8, 256>>>(ei);
    finalize2<<<(NN + 7) / 8, 256>>>(b2, aw, ab);

    // heads
    context_kernel<<<NG, 64>>>(cn, cc, sw, sb);
    softmax_kernel<<<NG, 1024>>>(masks, cc, out);
}

// round 5
// speedup vs baseline: 4.1557x; 4.1557x over previous
#include <cuda_runtime.h>

#define NN 50000
#define NE 800000
#define EE (NE + NN)
#define NG 32
#define KMAX 16
#define FIN 128
#define HID 64
#define HEADS 4
#define HC 256          // HEADS*HID
#define NP1 (NN + 1)
#define CAP 160         // per-node cached edge capacity (max degree ~40 expected)
#define NB_SCAN ((NN + 255) / 256)

// ---------------- scratch (static device globals; no allocation) ----------------
__device__ float    g_h1lin[NN * HC];    // x @ W1
__device__ float    g_h1   [NN * HC];    // after GAT1 + relu
__device__ float    g_h2lin[NN * HID];   // h1 @ W2
__device__ float    g_h2   [NN * HID];   // after GAT2 (+b2)
__device__ float    g_as1  [NN * HEADS];
__device__ float    g_ad1  [NN * HEADS];
__device__ float    g_as2  [NN];
__device__ float    g_ad2  [NN];
__device__ float    g_scores[NN];
__device__ float    g_stop  [NG];
__device__ int      g_ei64;
__device__ int      g_maskmode;          // 0=uint8, 1=int32, 2=float32

// CSR scratch (shared by both layers)
__device__ int      g_cnt [NN];
__device__ int      g_off [NN];
__device__ int      g_woff[NN];
__device__ int      g_csrc[EE];
__device__ int      g_bsum[NB_SCAN];
__device__ int      g_bsumoff[NB_SCAN];

// ---------------- helpers ----------------
__device__ __forceinline__ float lrelu(float a) { return a > 0.f ? a : 0.2f * a; }

__device__ __forceinline__ float warp_sum(float v) {
#pragma unroll
    for (int o = 16; o; o >>= 1) v += __shfl_xor_sync(0xffffffffu, v, o);
    return v;
}
__device__ __forceinline__ float warp_max(float v) {
#pragma unroll
    for (int o = 16; o; o >>= 1) v = fmaxf(v, __shfl_xor_sync(0xffffffffu, v, o));
    return v;
}

__device__ __forceinline__ void load_edge(const int* __restrict__ ei, int e, int& s, int& d) {
    if (e >= NE) { s = d = e - NE; return; }
    if (g_ei64) { s = ei[2 * e]; d = ei[2 * (NE + e)]; }
    else        { s = ei[e];     d = ei[NE + e]; }
}

__global__ void detect_ei(const unsigned* __restrict__ ei) {
    unsigned o = ei[1] | ei[3] | ei[5] | ei[7] | ei[9] | ei[11] | ei[13] | ei[15];
    g_ei64 = (o == 0u) ? 1 : 0;
}
__global__ void detect_masks(const unsigned* __restrict__ m) {
    int lane = threadIdx.x;
    int f32 = 0, multi = 0;
    for (int i = lane; i < 2048; i += 32) {
        unsigned w = m[i];
        if (w == 0x3F800000u) f32 = 1;
        else if (w > 1u) multi = 1;
    }
    f32 = __any_sync(0xffffffffu, f32);
    multi = __any_sync(0xffffffffu, multi);
    if (lane == 0) g_maskmode = f32 ? 2 : (multi ? 0 : 1);
}

// ---------------- CSR construction ----------------
__global__ void zero_cnt() {
    int i = blockIdx.x * blockDim.x + threadIdx.x;
    if (i < NN) g_cnt[i] = 0;
}
__global__ void hist_kernel(const int* __restrict__ ei) {
    int e = blockIdx.x * blockDim.x + threadIdx.x;
    if (e >= EE) return;
    int s, d;
    load_edge(ei, e, s, d);
    atomicAdd(&g_cnt[d], 1);
}
__global__ void scan1() {
    __shared__ int sh[256];
    int t = threadIdx.x;
    int i = blockIdx.x * 256 + t;
    int v = (i < NN) ? g_cnt[i] : 0;
    sh[t] = v;
    __syncthreads();
#pragma unroll
    for (int off = 1; off < 256; off <<= 1) {
        int add = (t >= off) ? sh[t - off] : 0;
        __syncthreads();
        sh[t] += add;
        __syncthreads();
    }
    if (i < NN) g_off[i] = sh[t] - v;        // exclusive within block
    if (t == 255) g_bsum[blockIdx.x] = sh[255];
}
__global__ void scan2() {
    __shared__ int sh[256];
    int t = threadIdx.x;
    int v = (t < NB_SCAN) ? g_bsum[t] : 0;
    sh[t] = v;
    __syncthreads();
#pragma unroll
    for (int off = 1; off < 256; off <<= 1) {
        int add = (t >= off) ? sh[t - off] : 0;
        __syncthreads();
        sh[t] += add;
        __syncthreads();
    }
    if (t < NB_SCAN) g_bsumoff[t] = sh[t] - v;  // exclusive across blocks
}
__global__ void scan3() {
    int i = blockIdx.x * blockDim.x + threadIdx.x;
    if (i >= NN) return;
    int o = g_off[i] + g_bsumoff[i >> 8];
    g_off[i] = o;
    g_woff[i] = o;
}
__global__ void fill_kernel(const int* __restrict__ ei) {
    int e = blockIdx.x * blockDim.x + threadIdx.x;
    if (e >= EE) return;
    int s, d;
    load_edge(ei, e, s, d);
    int pos = atomicAdd(&g_woff[d], 1);
    g_csrc[pos] = s;
}

// ---------------- SGEMM: C[M,N] = A[M,K] @ B[K,N], fp32 ----------------
__global__ void __launch_bounds__(256) sgemm64(const float* __restrict__ A,
                                               const float* __restrict__ B,
                                               float* __restrict__ C,
                                               int M, int N, int K) {
    const int BM = 64, BN = 64, BK = 16;
    __shared__ float As[BK][BM + 4];
    __shared__ float Bs[BK][BN];
    int tid = threadIdx.x;
    int bm = blockIdx.y * BM, bn = blockIdx.x * BN;
    int tx = tid & 15, ty = tid >> 4;

    int aRow = tid >> 2;
    int aCol = (tid & 3) * 4;
    int bRow = tid >> 4;
    int bCol = (tid & 15) * 4;

    float acc[4][4];
#pragma unroll
    for (int i = 0; i < 4; i++)
#pragma unroll
        for (int j = 0; j < 4; j++) acc[i][j] = 0.f;

    for (int k0 = 0; k0 < K; k0 += BK) {
        float4 av = make_float4(0.f, 0.f, 0.f, 0.f);
        if (bm + aRow < M)
            av = *(const float4*)&A[(size_t)(bm + aRow) * K + k0 + aCol];
        As[aCol + 0][aRow] = av.x;
        As[aCol + 1][aRow] = av.y;
        As[aCol + 2][aRow] = av.z;
        As[aCol + 3][aRow] = av.w;
        *(float4*)&Bs[bRow][bCol] = *(const float4*)&B[(size_t)(k0 + bRow) * N + bn + bCol];
        __syncthreads();
#pragma unroll
        for (int k = 0; k < BK; k++) {
            float4 a = *(const float4*)&As[k][ty * 4];
            float4 b = *(const float4*)&Bs[k][tx * 4];
            acc[0][0] += a.x * b.x; acc[0][1] += a.x * b.y; acc[0][2] += a.x * b.z; acc[0][3] += a.x * b.w;
            acc[1][0] += a.y * b.x; acc[1][1] += a.y * b.y; acc[1][2] += a.y * b.z; acc[1][3] += a.y * b.w;
            acc[2][0] += a.z * b.x; acc[2][1] += a.z * b.y; acc[2][2] += a.z * b.z; acc[2][3] += a.z * b.w;
            acc[3][0] += a.w * b.x; acc[3][1] += a.w * b.y; acc[3][2] += a.w * b.z; acc[3][3] += a.w * b.w;
        }
        __syncthreads();
    }
#pragma unroll
    for (int i = 0; i < 4; i++) {
        int r = bm + ty * 4 + i;
        if (r < M)
            *(float4*)&C[(size_t)r * N + bn + tx * 4] =
                make_float4(acc[i][0], acc[i][1], acc[i][2], acc[i][3]);
    }
}

// ---------------- attention dot products ----------------
__global__ void __launch_bounds__(256) prep1(const float* __restrict__ ws,
                                             const float* __restrict__ wd) {
    int w = (blockIdx.x * blockDim.x + threadIdx.x) >> 5;
    int lane = threadIdx.x & 31;
    if (w >= NN) return;
    const float4* hp = (const float4*)(g_h1lin + (size_t)w * HC + lane * 8);
    float4 v0 = hp[0], v1 = hp[1];
    const float4* sp = (const float4*)(ws + lane * 8);
    float4 s0 = sp[0], s1 = sp[1];
    const float4* dp = (const float4*)(wd + lane * 8);
    float4 d0 = dp[0], d1 = dp[1];
    float a = v0.x * s0.x + v0.y * s0.y + v0.z * s0.z + v0.w * s0.w
            + v1.x * s1.x + v1.y * s1.y + v1.z * s1.z + v1.w * s1.w;
    float b = v0.x * d0.x + v0.y * d0.y + v0.z * d0.z + v0.w * d0.w
            + v1.x * d1.x + v1.y * d1.y + v1.z * d1.z + v1.w * d1.w;
#pragma unroll
    for (int o = 4; o; o >>= 1) {
        a += __shfl_xor_sync(0xffffffffu, a, o);
        b += __shfl_xor_sync(0xffffffffu, b, o);
    }
    if ((lane & 7) == 0) {
        int h = lane >> 3;
        g_as1[(size_t)w * 4 + h] = a;
        g_ad1[(size_t)w * 4 + h] = b;
    }
}

__global__ void __launch_bounds__(256) prep2(const float* __restrict__ ws,
                                             const float* __restrict__ wd) {
    int w = (blockIdx.x * blockDim.x + threadIdx.x) >> 5;
    int lane = threadIdx.x & 31;
    if (w >= NN) return;
    float2 v = *(const float2*)(g_h2lin + (size_t)w * HID + lane * 2);
    float2 s = *(const float2*)(ws + lane * 2);
    float2 dd = *(const float2*)(wd + lane * 2);
    float a = warp_sum(v.x * s.x + v.y * s.y);
    float b = warp_sum(v.x * dd.x + v.y * dd.y);
    if (lane == 0) { g_as2[w] = a; g_ad2[w] = b; }
}

// ---------------- layer 1 gather: warp per dst node ----------------
__global__ void __launch_bounds__(256) node1_kernel(const float* __restrict__ b1) {
    __shared__ float s_ex[8][CAP * 4];
    __shared__ int   s_src[8][CAP];
    int w = (blockIdx.x * blockDim.x + threadIdx.x) >> 5;
    int lane = threadIdx.x & 31;
    int wl = threadIdx.x >> 5;
    if (w >= NN) return;
    int base = g_off[w];
    int deg  = g_cnt[w];
    float4 ad = *(const float4*)(g_ad1 + (size_t)w * 4);

    // pass 1: e per edge per head; warp max
    float4 mx = make_float4(-3.4e38f, -3.4e38f, -3.4e38f, -3.4e38f);
    for (int j = lane; j < deg; j += 32) {
        int s = g_csrc[base + j];
        float4 as = *(const float4*)(g_as1 + (size_t)s * 4);
        float4 e;
        e.x = lrelu(as.x + ad.x); e.y = lrelu(as.y + ad.y);
        e.z = lrelu(as.z + ad.z); e.w = lrelu(as.w + ad.w);
        if (j < CAP) {
            s_src[wl][j] = s;
            *(float4*)&s_ex[wl][j * 4] = e;
        }
        mx.x = fmaxf(mx.x, e.x); mx.y = fmaxf(mx.y, e.y);
        mx.z = fmaxf(mx.z, e.z); mx.w = fmaxf(mx.w, e.w);
    }
    mx.x = warp_max(mx.x); mx.y = warp_max(mx.y);
    mx.z = warp_max(mx.z); mx.w = warp_max(mx.w);
    __syncwarp();

    // pass 2: ex + denominator
    float4 den = make_float4(0.f, 0.f, 0.f, 0.f);
    for (int j = lane; j < deg; j += 32) {
        float4 e;
        if (j < CAP) e = *(const float4*)&s_ex[wl][j * 4];
        else {
            int s = g_csrc[base + j];
            float4 as = *(const float4*)(g_as1 + (size_t)s * 4);
            e.x = lrelu(as.x + ad.x); e.y = lrelu(as.y + ad.y);
            e.z = lrelu(as.z + ad.z); e.w = lrelu(as.w + ad.w);
        }
        float4 ex;
        ex.x = __expf(e.x - mx.x); ex.y = __expf(e.y - mx.y);
        ex.z = __expf(e.z - mx.z); ex.w = __expf(e.w - mx.w);
        if (j < CAP) *(float4*)&s_ex[wl][j * 4] = ex;
        den.x += ex.x; den.y += ex.y; den.z += ex.z; den.w += ex.w;
    }
    den.x = warp_sum(den.x); den.y = warp_sum(den.y);
    den.z = warp_sum(den.z); den.w = warp_sum(den.w);
    __syncwarp();

    // pass 3: feature accumulation (lane owns 8 features, head = lane/8)
    int head = lane >> 3;
    float mh = head == 0 ? mx.x : head == 1 ? mx.y : head == 2 ? mx.z : mx.w;
    float adh = head == 0 ? ad.x : head == 1 ? ad.y : head == 2 ? ad.z : ad.w;
    float dh = head == 0 ? den.x : head == 1 ? den.y : head == 2 ? den.z : den.w;
    float acc[8];
#pragma unroll
    for (int i = 0; i < 8; i++) acc[i] = 0.f;
    for (int j = 0; j < deg; j++) {
        int s; float ex;
        if (j < CAP) {
            s = s_src[wl][j];
            ex = s_ex[wl][j * 4 + head];
        } else {
            s = g_csrc[base + j];
            ex = __expf(lrelu(g_as1[(size_t)s * 4 + head] + adh) - mh);
        }
        const float4* hp = (const float4*)(g_h1lin + (size_t)s * HC + lane * 8);
        float4 v0 = hp[0], v1 = hp[1];
        acc[0] += ex * v0.x; acc[1] += ex * v0.y; acc[2] += ex * v0.z; acc[3] += ex * v0.w;
        acc[4] += ex * v1.x; acc[5] += ex * v1.y; acc[6] += ex * v1.z; acc[7] += ex * v1.w;
    }
    float inv = 1.f / dh;
    int f = lane * 8;
    const float4* bp = (const float4*)(b1 + f);
    float4 bb0 = bp[0], bb1 = bp[1];
    float4 o0, o1;
    o0.x = fmaxf(acc[0] * inv + bb0.x, 0.f);
    o0.y = fmaxf(acc[1] * inv + bb0.y, 0.f);
    o0.z = fmaxf(acc[2] * inv + bb0.z, 0.f);
    o0.w = fmaxf(acc[3] * inv + bb0.w, 0.f);
    o1.x = fmaxf(acc[4] * inv + bb1.x, 0.f);
    o1.y = fmaxf(acc[5] * inv + bb1.y, 0.f);
    o1.z = fmaxf(acc[6] * inv + bb1.z, 0.f);
    o1.w = fmaxf(acc[7] * inv + bb1.w, 0.f);
    float4* op = (float4*)(g_h1 + (size_t)w * HC + f);
    op[0] = o0;
    op[1] = o1;
}

// ---------------- layer 2 gather + node scores: warp per dst node ----------------
__global__ void __launch_bounds__(256) node2_kernel(const float* __restrict__ b2,
                                                    const float* __restrict__ aw,
                                                    const float* __restrict__ ab) {
    __shared__ float s_ex[8][CAP];
    __shared__ int   s_src[8][CAP];
    int w = (blockIdx.x * blockDim.x + threadIdx.x) >> 5;
    int lane = threadIdx.x & 31;
    int wl = threadIdx.x >> 5;
    if (w >= NN) return;
    int base = g_off[w];
    int deg  = g_cnt[w];
    float ad = g_ad2[w];

    float mx = -3.4e38f;
    for (int j = lane; j < deg; j += 32) {
        int s = g_csrc[base + j];
        float e = lrelu(g_as2[s] + ad);
        if (j < CAP) { s_src[wl][j] = s; s_ex[wl][j] = e; }
        mx = fmaxf(mx, e);
    }
    mx = warp_max(mx);
    __syncwarp();

    float den = 0.f;
    for (int j = lane; j < deg; j += 32) {
        float e = (j < CAP) ? s_ex[wl][j]
                            : lrelu(g_as2[g_csrc[base + j]] + ad);
        float ex = __expf(e - mx);
        if (j < CAP) s_ex[wl][j] = ex;
        den += ex;
    }
    den = warp_sum(den);
    __syncwarp();

    float acc0 = 0.f, acc1 = 0.f;
    for (int j = 0; j < deg; j++) {
        int s; float ex;
        if (j < CAP) { s = s_src[wl][j]; ex = s_ex[wl][j]; }
        else {
            s = g_csrc[base + j];
            ex = __expf(lrelu(g_as2[s] + ad) - mx);
        }
        float2 v = *(const float2*)(g_h2lin + (size_t)s * HID + lane * 2);
        acc0 += ex * v.x;
        acc1 += ex * v.y;
    }
    float inv = 1.f / den;
    int c = lane * 2;
    float h0 = acc0 * inv + b2[c];
    float h1 = acc1 * inv + b2[c + 1];
    *(float2*)(g_h2 + (size_t)w * HID + c) = make_float2(h0, h1);
    float sc = warp_sum(h0 * aw[c] + h1 * aw[c + 1]);
    if (lane == 0) g_scores[w] = tanhf(sc + ab[0]);
}

// ---------------- per-graph pooled stop score ----------------
__global__ void context_kernel(const int* __restrict__ cn, const int* __restrict__ cc,
                               const float* __restrict__ sw, const float* __restrict__ sb) {
    int g = blockIdx.x;
    int c = threadIdx.x;   // 64 threads
    int cnt = cc[g];
    float sum = 0.f;
#pragma unroll
    for (int k = 0; k < KMAX; k++) {
        if (k < cnt) {
            int n = cn[g * KMAX + k];
            sum += g_h2[(size_t)n * HID + c];
        }
    }
    int cm = cnt > 1 ? cnt : 1;
    float ctx = sum / (float)cm;
    __shared__ float red[64];
    red[c] = ctx * sw[c];
    __syncthreads();
    for (int o = 32; o; o >>= 1) {
        if (c < o) red[c] += red[c + o];
        __syncthreads();
    }
    if (c == 0) g_stop[g] = tanhf(red[0] + sb[0]);
}

__device__ __forceinline__ bool get_mask(const void* masks, int mode, int g, int i) {
    if (mode == 2) return ((const float*)masks)[(size_t)g * NN + i] != 0.f;
    if (mode == 1) return ((const int*)masks)[(size_t)g * NN + i] != 0;
    return ((const unsigned char*)masks)[(size_t)g * NN + i] != 0;
}

// ---------------- per-graph masked softmax over N+1 ----------------
__global__ void __launch_bounds__(1024) softmax_kernel(const void* __restrict__ masks,
                                                       const int* __restrict__ cc,
                                                       float* __restrict__ out) {
    int g = blockIdx.x;
    int tid = threadIdx.x;
    int lane = tid & 31, wid = tid >> 5;
    int mode = g_maskmode;
    float* o = out + (size_t)g * NP1;
    if (cc[g] == 0) {
        for (int i = tid; i < NP1; i += 1024) o[i] = (i == NN) ? 1.f : 0.f;
        return;
    }
    __shared__ float sm[32];
    __shared__ float bc[2];

    float mx = -3.4e38f;
    for (int i = tid; i < NN; i += 1024) {
        float s = get_mask(masks, mode, g, i) ? g_scores[i] : -1e9f;
        mx = fmaxf(mx, s);
    }
    mx = warp_max(mx);
    if (lane == 0) sm[wid] = mx;
    __syncthreads();
    if (wid == 0) {
        float v = warp_max(sm[lane]);
        if (lane == 0) bc[0] = fmaxf(v, g_stop[g]);
    }
    __syncthreads();
    mx = bc[0];

    float sum = 0.f;
    for (int i = tid; i < NN; i += 1024) {
        float s = get_mask(masks, mode, g, i) ? g_scores[i] : -1e9f;
        sum += __expf(s - mx);
    }
    sum = warp_sum(sum);
    __syncthreads();
    if (lane == 0) sm[wid] = sum;
    __syncthreads();
    if (wid == 0) {
        float v = warp_sum(sm[lane]);
        if (lane == 0) bc[1] = v + __expf(g_stop[g] - mx);
    }
    __syncthreads();
    float inv = 1.f / bc[1];

    for (int i = tid; i < NN; i += 1024) {
        float s = get_mask(masks, mode, g, i) ? g_scores[i] : -1e9f;
        o[i] = __expf(s - mx) * inv;
    }
    if (tid == 0) o[NN] = __expf(g_stop[g] - mx) * inv;
}

// ---------------- host ----------------
extern "C" void kernel_launch(void* const* d_in, const int* in_sizes, int n_in,
                              void* d_out, int out_size) {
    const float* x    = (const float*)d_in[0];
    const int*   ei   = (const int*)d_in[1];
    const int*   cn   = (const int*)d_in[2];
    const int*   cc   = (const int*)d_in[3];
    const void*  masks = d_in[4];
    const float* W1   = (const float*)d_in[5];
    const float* as1w = (const float*)d_in[6];
    const float* ad1w = (const float*)d_in[7];
    const float* b1   = (const float*)d_in[8];
    const float* W2   = (const float*)d_in[9];
    const float* as2w = (const float*)d_in[10];
    const float* ad2w = (const float*)d_in[11];
    const float* b2   = (const float*)d_in[12];
    const float* aw   = (const float*)d_in[13];
    const float* ab   = (const float*)d_in[14];
    const float* sw   = (const float*)d_in[15];
    const float* sb   = (const float*)d_in[16];
    float* out = (float*)d_out;

    float *h1lin_p, *h1_p, *h2lin_p;
    cudaGetSymbolAddress((void**)&h1lin_p, g_h1lin);
    cudaGetSymbolAddress((void**)&h1_p, g_h1);
    cudaGetSymbolAddress((void**)&h2lin_p, g_h2lin);

    detect_ei<<<1, 1>>>((const unsigned*)ei);
    detect_masks<<<1, 32>>>((const unsigned*)masks);

    // CSR build (reused by both layers)
    zero_cnt<<<(NN + 255) / 256, 256>>>();
    hist_kernel<<<(EE + 255) / 256, 256>>>(ei);
    scan1<<<NB_SCAN, 256>>>();
    scan2<<<1, 256>>>();
    scan3<<<NB_SCAN, 256>>>();
    fill_kernel<<<(EE + 255) / 256, 256>>>(ei);

    // layer 1
    sgemm64<<<dim3(HC / 64, (NN + 63) / 64), 256>>>(x, W1, h1lin_p, NN, HC, FIN);
    prep1<<<(NN + 7) / 8, 256>>>(as1w, ad1w);
    node1_kernel<<<(NN + 7) / 8, 256>>>(b1);

    // layer 2
    sgemm64<<<dim3(HID / 64, (NN + 63) / 64), 256>>>(h1_p, W2, h2lin_p, NN, HID, HC);
    prep2<<<(NN + 7) / 8, 256>>>(as2w, ad2w);
    node2_kernel<<<(NN + 7) / 8, 256>>>(b2, aw, ab);

    // heads
    context_kernel<<<NG, 64>>>(cn, cc, sw, sb);
    softmax_kernel<<<NG, 1024>>>(masks, cc, out);
}

// round 6
// speedup vs baseline: 5.1789x; 1.2462x over previous
#include <cuda_runtime.h>
#include <cuda_bf16.h>

#define NN 50000
#define NE 800000
#define EE (NE + NN)
#define NG 32
#define KMAX 16
#define FIN 128
#define HID 64
#define HEADS 4
#define HC 256          // HEADS*HID
#define NP1 (NN + 1)
#define CAP 160         // per-node cached edge capacity
#define NB_SCAN ((NN + 255) / 256)

// ---------------- scratch (static device globals; no allocation) ----------------
__device__ float         g_h1lin[NN * HC];    // x @ W1 (fp32)
__device__ __nv_bfloat16 g_h1bf [NN * HC];    // bf16 copy for the edge gather
__device__ float         g_h1   [NN * HC];    // after GAT1 + relu
__device__ float         g_h2lin[NN * HID];   // h1 @ W2
__device__ float         g_h2   [NN * HID];   // after GAT2 (+b2)
__device__ float         g_as1  [NN * HEADS];
__device__ float         g_ad1  [NN * HEADS];
__device__ float         g_as2  [NN];
__device__ float         g_ad2  [NN];
__device__ float         g_scores[NN];
__device__ float         g_stop  [NG];
__device__ int           g_ei64;
__device__ int           g_maskmode;          // 0=uint8, 1=int32, 2=float32

// CSR scratch
__device__ int g_cnt [NN];
__device__ int g_off [NN];
__device__ int g_woff[NN];
__device__ int g_csrc[EE];
__device__ int g_bsum[NB_SCAN];
__device__ int g_bsumoff[NB_SCAN];

// ---------------- helpers ----------------
__device__ __forceinline__ float lrelu(float a) { return a > 0.f ? a : 0.2f * a; }

__device__ __forceinline__ float warp_sum(float v) {
#pragma unroll
    for (int o = 16; o; o >>= 1) v += __shfl_xor_sync(0xffffffffu, v, o);
    return v;
}
__device__ __forceinline__ float warp_max(float v) {
#pragma unroll
    for (int o = 16; o; o >>= 1) v = fmaxf(v, __shfl_xor_sync(0xffffffffu, v, o));
    return v;
}

__device__ __forceinline__ void load_edge(const int* __restrict__ ei, int e, int& s, int& d) {
    if (e >= NE) { s = d = e - NE; return; }
    if (g_ei64) { s = ei[2 * e]; d = ei[2 * (NE + e)]; }
    else        { s = ei[e];     d = ei[NE + e]; }
}

__global__ void detect_ei(const unsigned* __restrict__ ei) {
    unsigned o = ei[1] | ei[3] | ei[5] | ei[7] | ei[9] | ei[11] | ei[13] | ei[15];
    g_ei64 = (o == 0u) ? 1 : 0;
}
__global__ void detect_masks(const unsigned* __restrict__ m) {
    int lane = threadIdx.x;
    int f32 = 0, multi = 0;
    for (int i = lane; i < 2048; i += 32) {
        unsigned w = m[i];
        if (w == 0x3F800000u) f32 = 1;
        else if (w > 1u) multi = 1;
    }
    f32 = __any_sync(0xffffffffu, f32);
    multi = __any_sync(0xffffffffu, multi);
    if (lane == 0) g_maskmode = f32 ? 2 : (multi ? 0 : 1);
}

// ---------------- CSR construction ----------------
__global__ void zero_cnt() {
    int i = blockIdx.x * blockDim.x + threadIdx.x;
    if (i < NN) g_cnt[i] = 0;
}
__global__ void hist_kernel(const int* __restrict__ ei) {
    int e = blockIdx.x * blockDim.x + threadIdx.x;
    if (e >= EE) return;
    int s, d;
    load_edge(ei, e, s, d);
    atomicAdd(&g_cnt[d], 1);
}
__global__ void scan1() {
    __shared__ int sh[256];
    int t = threadIdx.x;
    int i = blockIdx.x * 256 + t;
    int v = (i < NN) ? g_cnt[i] : 0;
    sh[t] = v;
    __syncthreads();
#pragma unroll
    for (int off = 1; off < 256; off <<= 1) {
        int add = (t >= off) ? sh[t - off] : 0;
        __syncthreads();
        sh[t] += add;
        __syncthreads();
    }
    if (i < NN) g_off[i] = sh[t] - v;
    if (t == 255) g_bsum[blockIdx.x] = sh[255];
}
__global__ void scan2() {
    __shared__ int sh[256];
    int t = threadIdx.x;
    int v = (t < NB_SCAN) ? g_bsum[t] : 0;
    sh[t] = v;
    __syncthreads();
#pragma unroll
    for (int off = 1; off < 256; off <<= 1) {
        int add = (t >= off) ? sh[t - off] : 0;
        __syncthreads();
        sh[t] += add;
        __syncthreads();
    }
    if (t < NB_SCAN) g_bsumoff[t] = sh[t] - v;
}
__global__ void scan3() {
    int i = blockIdx.x * blockDim.x + threadIdx.x;
    if (i >= NN) return;
    int o = g_off[i] + g_bsumoff[i >> 8];
    g_off[i] = o;
    g_woff[i] = o;
}
__global__ void fill_kernel(const int* __restrict__ ei) {
    int e = blockIdx.x * blockDim.x + threadIdx.x;
    if (e >= EE) return;
    int s, d;
    load_edge(ei, e, s, d);
    int pos = atomicAdd(&g_woff[d], 1);
    g_csrc[pos] = s;
}

// ---------------- SGEMM: C[M,N] = A[M,K] @ B[K,N], BM=128 BN=64 BK=16 TM=8 TN=4 ----------------
__global__ void __launch_bounds__(256) sgemm128(const float* __restrict__ A,
                                                const float* __restrict__ B,
                                                float* __restrict__ C,
                                                int M, int N, int K) {
    const int BM = 128, BN = 64, BK = 16;
    __shared__ float As[BK][BM + 4];
    __shared__ float Bs[BK][BN];
    int tid = threadIdx.x;
    int bm = blockIdx.y * BM, bn = blockIdx.x * BN;
    int tx = tid & 15, ty = tid >> 4;      // tx: 0..15 (N), ty: 0..15 (M)

    int aRow = tid >> 2;                   // 0..63
    int aCol = (tid & 3) * 4;              // 0,4,8,12
    int bRow = tid >> 4;                   // 0..15
    int bCol = (tid & 15) * 4;             // 0..60

    float acc[8][4];
#pragma unroll
    for (int i = 0; i < 8; i++)
#pragma unroll
        for (int j = 0; j < 4; j++) acc[i][j] = 0.f;

    for (int k0 = 0; k0 < K; k0 += BK) {
        float4 av0 = make_float4(0.f, 0.f, 0.f, 0.f);
        float4 av1 = av0;
        if (bm + aRow < M)
            av0 = *(const float4*)&A[(size_t)(bm + aRow) * K + k0 + aCol];
        if (bm + aRow + 64 < M)
            av1 = *(const float4*)&A[(size_t)(bm + aRow + 64) * K + k0 + aCol];
        As[aCol + 0][aRow] = av0.x;  As[aCol + 0][aRow + 64] = av1.x;
        As[aCol + 1][aRow] = av0.y;  As[aCol + 1][aRow + 64] = av1.y;
        As[aCol + 2][aRow] = av0.z;  As[aCol + 2][aRow + 64] = av1.z;
        As[aCol + 3][aRow] = av0.w;  As[aCol + 3][aRow + 64] = av1.w;
        *(float4*)&Bs[bRow][bCol] = *(const float4*)&B[(size_t)(k0 + bRow) * N + bn + bCol];
        __syncthreads();
#pragma unroll
        for (int k = 0; k < BK; k++) {
            float4 a0 = *(const float4*)&As[k][ty * 8];
            float4 a1 = *(const float4*)&As[k][ty * 8 + 4];
            float4 b  = *(const float4*)&Bs[k][tx * 4];
            acc[0][0] += a0.x * b.x; acc[0][1] += a0.x * b.y; acc[0][2] += a0.x * b.z; acc[0][3] += a0.x * b.w;
            acc[1][0] += a0.y * b.x; acc[1][1] += a0.y * b.y; acc[1][2] += a0.y * b.z; acc[1][3] += a0.y * b.w;
            acc[2][0] += a0.z * b.x; acc[2][1] += a0.z * b.y; acc[2][2] += a0.z * b.z; acc[2][3] += a0.z * b.w;
            acc[3][0] += a0.w * b.x; acc[3][1] += a0.w * b.y; acc[3][2] += a0.w * b.z; acc[3][3] += a0.w * b.w;
            acc[4][0] += a1.x * b.x; acc[4][1] += a1.x * b.y; acc[4][2] += a1.x * b.z; acc[4][3] += a1.x * b.w;
            acc[5][0] += a1.y * b.x; acc[5][1] += a1.y * b.y; acc[5][2] += a1.y * b.z; acc[5][3] += a1.y * b.w;
            acc[6][0] += a1.z * b.x; acc[6][1] += a1.z * b.y; acc[6][2] += a1.z * b.z; acc[6][3] += a1.z * b.w;
            acc[7][0] += a1.w * b.x; acc[7][1] += a1.w * b.y; acc[7][2] += a1.w * b.z; acc[7][3] += a1.w * b.w;
        }
        __syncthreads();
    }
#pragma unroll
    for (int i = 0; i < 8; i++) {
        int r = bm + ty * 8 + i;
        if (r < M)
            *(float4*)&C[(size_t)r * N + bn + tx * 4] =
                make_float4(acc[i][0], acc[i][1], acc[i][2], acc[i][3]);
    }
}

// ---------------- attention dot products (+ bf16 copy of h1lin) ----------------
__global__ void __launch_bounds__(256) prep1(const float* __restrict__ ws,
                                             const float* __restrict__ wd) {
    int w = (blockIdx.x * blockDim.x + threadIdx.x) >> 5;
    int lane = threadIdx.x & 31;
    if (w >= NN) return;
    const float4* hp = (const float4*)(g_h1lin + (size_t)w * HC + lane * 8);
    float4 v0 = hp[0], v1 = hp[1];

    // bf16 copy for the gather pass
    __nv_bfloat162 q0 = __floats2bfloat162_rn(v0.x, v0.y);
    __nv_bfloat162 q1 = __floats2bfloat162_rn(v0.z, v0.w);
    __nv_bfloat162 q2 = __floats2bfloat162_rn(v1.x, v1.y);
    __nv_bfloat162 q3 = __floats2bfloat162_rn(v1.z, v1.w);
    uint4 pk;
    pk.x = *(unsigned*)&q0; pk.y = *(unsigned*)&q1;
    pk.z = *(unsigned*)&q2; pk.w = *(unsigned*)&q3;
    *(uint4*)(g_h1bf + (size_t)w * HC + lane * 8) = pk;

    const float4* sp = (const float4*)(ws + lane * 8);
    float4 s0 = sp[0], s1 = sp[1];
    const float4* dp = (const float4*)(wd + lane * 8);
    float4 d0 = dp[0], d1 = dp[1];
    float a = v0.x * s0.x + v0.y * s0.y + v0.z * s0.z + v0.w * s0.w
            + v1.x * s1.x + v1.y * s1.y + v1.z * s1.z + v1.w * s1.w;
    float b = v0.x * d0.x + v0.y * d0.y + v0.z * d0.z + v0.w * d0.w
            + v1.x * d1.x + v1.y * d1.y + v1.z * d1.z + v1.w * d1.w;
#pragma unroll
    for (int o = 4; o; o >>= 1) {
        a += __shfl_xor_sync(0xffffffffu, a, o);
        b += __shfl_xor_sync(0xffffffffu, b, o);
    }
    if ((lane & 7) == 0) {
        int h = lane >> 3;
        g_as1[(size_t)w * 4 + h] = a;
        g_ad1[(size_t)w * 4 + h] = b;
    }
}

__global__ void __launch_bounds__(256) prep2(const float* __restrict__ ws,
                                             const float* __restrict__ wd) {
    int w = (blockIdx.x * blockDim.x + threadIdx.x) >> 5;
    int lane = threadIdx.x & 31;
    if (w >= NN) return;
    float2 v = *(const float2*)(g_h2lin + (size_t)w * HID + lane * 2);
    float2 s = *(const float2*)(ws + lane * 2);
    float2 dd = *(const float2*)(wd + lane * 2);
    float a = warp_sum(v.x * s.x + v.y * s.y);
    float b = warp_sum(v.x * dd.x + v.y * dd.y);
    if (lane == 0) { g_as2[w] = a; g_ad2[w] = b; }
}

// ---------------- layer 1 gather: warp per dst node ----------------
__global__ void __launch_bounds__(256) node1_kernel(const float* __restrict__ b1) {
    __shared__ float s_ex[8][CAP * 4];
    __shared__ int   s_src[8][CAP];
    int w = (blockIdx.x * blockDim.x + threadIdx.x) >> 5;
    int lane = threadIdx.x & 31;
    int wl = threadIdx.x >> 5;
    if (w >= NN) return;
    int base = g_off[w];
    int deg  = g_cnt[w];
    float4 ad = *(const float4*)(g_ad1 + (size_t)w * 4);

    // pass 1: e per edge per head; warp max
    float4 mx = make_float4(-3.4e38f, -3.4e38f, -3.4e38f, -3.4e38f);
    for (int j = lane; j < deg; j += 32) {
        int s = g_csrc[base + j];
        float4 as = *(const float4*)(g_as1 + (size_t)s * 4);
        float4 e;
        e.x = lrelu(as.x + ad.x); e.y = lrelu(as.y + ad.y);
        e.z = lrelu(as.z + ad.z); e.w = lrelu(as.w + ad.w);
        if (j < CAP) {
            s_src[wl][j] = s;
            *(float4*)&s_ex[wl][j * 4] = e;
        }
        mx.x = fmaxf(mx.x, e.x); mx.y = fmaxf(mx.y, e.y);
        mx.z = fmaxf(mx.z, e.z); mx.w = fmaxf(mx.w, e.w);
    }
    mx.x = warp_max(mx.x); mx.y = warp_max(mx.y);
    mx.z = warp_max(mx.z); mx.w = warp_max(mx.w);
    __syncwarp();

    // pass 2: ex + denominator
    float4 den = make_float4(0.f, 0.f, 0.f, 0.f);
    for (int j = lane; j < deg; j += 32) {
        float4 e;
        if (j < CAP) e = *(const float4*)&s_ex[wl][j * 4];
        else {
            int s = g_csrc[base + j];
            float4 as = *(const float4*)(g_as1 + (size_t)s * 4);
            e.x = lrelu(as.x + ad.x); e.y = lrelu(as.y + ad.y);
            e.z = lrelu(as.z + ad.z); e.w = lrelu(as.w + ad.w);
        }
        float4 ex;
        ex.x = __expf(e.x - mx.x); ex.y = __expf(e.y - mx.y);
        ex.z = __expf(e.z - mx.z); ex.w = __expf(e.w - mx.w);
        if (j < CAP) *(float4*)&s_ex[wl][j * 4] = ex;
        den.x += ex.x; den.y += ex.y; den.z += ex.z; den.w += ex.w;
    }
    den.x = warp_sum(den.x); den.y = warp_sum(den.y);
    den.z = warp_sum(den.z); den.w = warp_sum(den.w);
    __syncwarp();

    // pass 3: feature accumulation, bf16 source rows (lane owns 8 features, head = lane/8)
    int head = lane >> 3;
    float mh  = head == 0 ? mx.x : head == 1 ? mx.y : head == 2 ? mx.z : mx.w;
    float adh = head == 0 ? ad.x : head == 1 ? ad.y : head == 2 ? ad.z : ad.w;
    float dh  = head == 0 ? den.x : head == 1 ? den.y : head == 2 ? den.z : den.w;
    float acc[8];
#pragma unroll
    for (int i = 0; i < 8; i++) acc[i] = 0.f;
    for (int j = 0; j < deg; j++) {
        int s; float ex;
        if (j < CAP) {
            s = s_src[wl][j];
            ex = s_ex[wl][j * 4 + head];
        } else {
            s = g_csrc[base + j];
            ex = __expf(lrelu(g_as1[(size_t)s * 4 + head] + adh) - mh);
        }
        uint4 r = *(const uint4*)(g_h1bf + (size_t)s * HC + lane * 8);
        float2 f0 = __bfloat1622float2(*(const __nv_bfloat162*)&r.x);
        float2 f1 = __bfloat1622float2(*(const __nv_bfloat162*)&r.y);
        float2 f2 = __bfloat1622float2(*(const __nv_bfloat162*)&r.z);
        float2 f3 = __bfloat1622float2(*(const __nv_bfloat162*)&r.w);
        acc[0] += ex * f0.x; acc[1] += ex * f0.y;
        acc[2] += ex * f1.x; acc[3] += ex * f1.y;
        acc[4] += ex * f2.x; acc[5] += ex * f2.y;
        acc[6] += ex * f3.x; acc[7] += ex * f3.y;
    }
    float inv = 1.f / dh;
    int f = lane * 8;
    const float4* bp = (const float4*)(b1 + f);
    float4 bb0 = bp[0], bb1 = bp[1];
    float4 o0, o1;
    o0.x = fmaxf(acc[0] * inv + bb0.x, 0.f);
    o0.y = fmaxf(acc[1] * inv + bb0.y, 0.f);
    o0.z = fmaxf(acc[2] * inv + bb0.z, 0.f);
    o0.w = fmaxf(acc[3] * inv + bb0.w, 0.f);
    o1.x = fmaxf(acc[4] * inv + bb1.x, 0.f);
    o1.y = fmaxf(acc[5] * inv + bb1.y, 0.f);
    o1.z = fmaxf(acc[6] * inv + bb1.z, 0.f);
    o1.w = fmaxf(acc[7] * inv + bb1.w, 0.f);
    float4* op = (float4*)(g_h1 + (size_t)w * HC + f);
    op[0] = o0;
    op[1] = o1;
}

// ---------------- layer 2 gather + node scores: warp per dst node ----------------
__global__ void __launch_bounds__(256) node2_kernel(const float* __restrict__ b2,
                                                    const float* __restrict__ aw,
                                                    const float* __restrict__ ab) {
    __shared__ float s_ex[8][CAP];
    __shared__ int   s_src[8][CAP];
    int w = (blockIdx.x * blockDim.x + threadIdx.x) >> 5;
    int lane = threadIdx.x & 31;
    int wl = threadIdx.x >> 5;
    if (w >= NN) return;
    int base = g_off[w];
    int deg  = g_cnt[w];
    float ad = g_ad2[w];

    float mx = -3.4e38f;
    for (int j = lane; j < deg; j += 32) {
        int s = g_csrc[base + j];
        float e = lrelu(g_as2[s] + ad);
        if (j < CAP) { s_src[wl][j] = s; s_ex[wl][j] = e; }
        mx = fmaxf(mx, e);
    }
    mx = warp_max(mx);
    __syncwarp();

    float den = 0.f;
    for (int j = lane; j < deg; j += 32) {
        float e = (j < CAP) ? s_ex[wl][j]
                            : lrelu(g_as2[g_csrc[base + j]] + ad);
        float ex = __expf(e - mx);
        if (j < CAP) s_ex[wl][j] = ex;
        den += ex;
    }
    den = warp_sum(den);
    __syncwarp();

    float acc0 = 0.f, acc1 = 0.f;
    for (int j = 0; j < deg; j++) {
        int s; float ex;
        if (j < CAP) { s = s_src[wl][j]; ex = s_ex[wl][j]; }
        else {
            s = g_csrc[base + j];
            ex = __expf(lrelu(g_as2[s] + ad) - mx);
        }
        float2 v = *(const float2*)(g_h2lin + (size_t)s * HID + lane * 2);
        acc0 += ex * v.x;
        acc1 += ex * v.y;
    }
    float inv = 1.f / den;
    int c = lane * 2;
    float h0 = acc0 * inv + b2[c];
    float h1 = acc1 * inv + b2[c + 1];
    *(float2*)(g_h2 + (size_t)w * HID + c) = make_float2(h0, h1);
    float sc = warp_sum(h0 * aw[c] + h1 * aw[c + 1]);
    if (lane == 0) g_scores[w] = tanhf(sc + ab[0]);
}

// ---------------- per-graph pooled stop score ----------------
__global__ void context_kernel(const int* __restrict__ cn, const int* __restrict__ cc,
                               const float* __restrict__ sw, const float* __restrict__ sb) {
    int g = blockIdx.x;
    int c = threadIdx.x;   // 64 threads
    int cnt = cc[g];
    float sum = 0.f;
#pragma unroll
    for (int k = 0; k < KMAX; k++) {
        if (k < cnt) {
            int n = cn[g * KMAX + k];
            sum += g_h2[(size_t)n * HID + c];
        }
    }
    int cm = cnt > 1 ? cnt : 1;
    float ctx = sum / (float)cm;
    __shared__ float red[64];
    red[c] = ctx * sw[c];
    __syncthreads();
    for (int o = 32; o; o >>= 1) {
        if (c < o) red[c] += red[c + o];
        __syncthreads();
    }
    if (c == 0) g_stop[g] = tanhf(red[0] + sb[0]);
}

__device__ __forceinline__ bool get_mask(const void* masks, int mode, int g, int i) {
    if (mode == 2) return ((const float*)masks)[(size_t)g * NN + i] != 0.f;
    if (mode == 1) return ((const int*)masks)[(size_t)g * NN + i] != 0;
    return ((const unsigned char*)masks)[(size_t)g * NN + i] != 0;
}

// ---------------- per-graph masked softmax over N+1 ----------------
__global__ void __launch_bounds__(1024) softmax_kernel(const void* __restrict__ masks,
                                                       const int* __restrict__ cc,
                                                       float* __restrict__ out) {
    int g = blockIdx.x;
    int tid = threadIdx.x;
    int lane = tid & 31, wid = tid >> 5;
    int mode = g_maskmode;
    float* o = out + (size_t)g * NP1;
    if (cc[g] == 0) {
        for (int i = tid; i < NP1; i += 1024) o[i] = (i == NN) ? 1.f : 0.f;
        return;
    }
    __shared__ float sm[32];
    __shared__ float bc[2];

    float mx = -3.4e38f;
    for (int i = tid; i < NN; i += 1024) {
        float s = get_mask(masks, mode, g, i) ? g_scores[i] : -1e9f;
        mx = fmaxf(mx, s);
    }
    mx = warp_max(mx);
    if (lane == 0) sm[wid] = mx;
    __syncthreads();
    if (wid == 0) {
        float v = warp_max(sm[lane]);
        if (lane == 0) bc[0] = fmaxf(v, g_stop[g]);
    }
    __syncthreads();
    mx = bc[0];

    float sum = 0.f;
    for (int i = tid; i < NN; i += 1024) {
        float s = get_mask(masks, mode, g, i) ? g_scores[i] : -1e9f;
        sum += __expf(s - mx);
    }
    sum = warp_sum(sum);
    __syncthreads();
    if (lane == 0) sm[wid] = sum;
    __syncthreads();
    if (wid == 0) {
        float v = warp_sum(sm[lane]);
        if (lane == 0) bc[1] = v + __expf(g_stop[g] - mx);
    }
    __syncthreads();
    float inv = 1.f / bc[1];

    for (int i = tid; i < NN; i += 1024) {
        float s = get_mask(masks, mode, g, i) ? g_scores[i] : -1e9f;
        o[i] = __expf(s - mx) * inv;
    }
    if (tid == 0) o[NN] = __expf(g_stop[g] - mx) * inv;
}

// ---------------- host ----------------
extern "C" void kernel_launch(void* const* d_in, const int* in_sizes, int n_in,
                              void* d_out, int out_size) {
    const float* x    = (const float*)d_in[0];
    const int*   ei   = (const int*)d_in[1];
    const int*   cn   = (const int*)d_in[2];
    const int*   cc   = (const int*)d_in[3];
    const void*  masks = d_in[4];
    const float* W1   = (const float*)d_in[5];
    const float* as1w = (const float*)d_in[6];
    const float* ad1w = (const float*)d_in[7];
    const float* b1   = (const float*)d_in[8];
    const float* W2   = (const float*)d_in[9];
    const float* as2w = (const float*)d_in[10];
    const float* ad2w = (const float*)d_in[11];
    const float* b2   = (const float*)d_in[12];
    const float* aw   = (const float*)d_in[13];
    const float* ab   = (const float*)d_in[14];
    const float* sw   = (const float*)d_in[15];
    const float* sb   = (const float*)d_in[16];
    float* out = (float*)d_out;

    float *h1lin_p, *h1_p, *h2lin_p;
    cudaGetSymbolAddress((void**)&h1lin_p, g_h1lin);
    cudaGetSymbolAddress((void**)&h1_p, g_h1);
    cudaGetSymbolAddress((void**)&h2lin_p, g_h2lin);

    static cudaStream_t s2 = nullptr;
    static cudaEvent_t evFork = nullptr, evJoin = nullptr;
    if (!s2) {
        cudaStreamCreateWithFlags(&s2, cudaStreamNonBlocking);
        cudaEventCreateWithFlags(&evFork, cudaEventDisableTiming);
        cudaEventCreateWithFlags(&evJoin, cudaEventDisableTiming);
    }

    detect_ei<<<1, 1>>>((const unsigned*)ei);
    detect_masks<<<1, 32>>>((const unsigned*)masks);

    // fork: CSR build on s2, GEMM1+prep1 on main
    cudaEventRecord(evFork, 0);
    cudaStreamWaitEvent(s2, evFork, 0);
    zero_cnt<<<(NN + 255) / 256, 256, 0, s2>>>();
    hist_kernel<<<(EE + 255) / 256, 256, 0, s2>>>(ei);
    scan1<<<NB_SCAN, 256, 0, s2>>>();
    scan2<<<1, 256, 0, s2>>>();
    scan3<<<NB_SCAN, 256, 0, s2>>>();
    fill_kernel<<<(EE + 255) / 256, 256, 0, s2>>>(ei);
    cudaEventRecord(evJoin, s2);

    sgemm128<<<dim3(HC / 64, (NN + 127) / 128), 256>>>(x, W1, h1lin_p, NN, HC, FIN);
    prep1<<<(NN + 7) / 8, 256>>>(as1w, ad1w);

    // join
    cudaStreamWaitEvent(0, evJoin, 0);
    node1_kernel<<<(NN + 7) / 8, 256>>>(b1);

    // layer 2
    sgemm128<<<dim3(HID / 64, (NN + 127) / 128), 256>>>(h1_p, W2, h2lin_p, NN, HID, HC);
    prep2<<<(NN + 7) / 8, 256>>>(as2w, ad2w);
    node2_kernel<<<(NN + 7) / 8, 256>>>(b2, aw, ab);

    // heads
    context_kernel<<<NG, 64>>>(cn, cc, sw, sb);
    softmax_kernel<<<NG, 1024>>>(masks, cc, out);
}

// round 9
// speedup vs baseline: 6.8285x; 1.3185x over previous
#include <cuda_runtime.h>
#include <cuda_bf16.h>

#define NN 50000
#define NE 800000
#define EE (NE + NN)
#define NG 32
#define KMAX 16
#define FIN 128
#define HID 64
#define HEADS 4
#define HC 256          // HEADS*HID
#define NP1 (NN + 1)
#define CAP 160
#define NB_SCAN ((NN + 255) / 256)
#define SCH 8
#define CHUNK (NN / SCH)   // 6250

// ---------------- scratch ----------------
__device__ __nv_bfloat16 g_h1bf[NN * HC];    // x@W1 in bf16 (gather operand)
__device__ float         g_h1  [NN * HC];    // after GAT1 + relu (GEMM2 input)
__device__ __nv_bfloat16 g_h2bf[NN * HID];   // h1@W2 in bf16 (gather operand)
__device__ float         g_h2  [NN * HID];   // after GAT2 (+b2)
__device__ float         g_as1 [NN * HEADS];
__device__ float         g_ad1 [NN * HEADS];
__device__ float         g_as2 [NN];
__device__ float         g_ad2 [NN];
__device__ float         g_scores[NN];
__device__ float         g_stop  [NG];
__device__ int           g_ei64;
__device__ int           g_maskmode;         // 0=uint8, 1=int32, 2=float32

// CSR scratch
__device__ int g_cnt [NN];
__device__ int g_off [NN];
__device__ int g_woff[NN];
__device__ int g_csrc[EE];
__device__ int g_bsum[NB_SCAN];
__device__ int g_bsumoff[NB_SCAN];

// softmax partials
__device__ float g_pm[NG * SCH];
__device__ float g_ps[NG * SCH];
__device__ float g_smx[NG];
__device__ float g_sinv[NG];

// ---------------- helpers ----------------
__device__ __forceinline__ float lrelu(float a) { return a > 0.f ? a : 0.2f * a; }

__device__ __forceinline__ float warp_sum(float v) {
#pragma unroll
    for (int o = 16; o; o >>= 1) v += __shfl_xor_sync(0xffffffffu, v, o);
    return v;
}
__device__ __forceinline__ float warp_max(float v) {
#pragma unroll
    for (int o = 16; o; o >>= 1) v = fmaxf(v, __shfl_xor_sync(0xffffffffu, v, o));
    return v;
}

__device__ __forceinline__ unsigned f2tf(float f) {
    unsigned u;
    asm("cvt.rna.tf32.f32 %0, %1;" : "=r"(u) : "f"(f));
    return u;
}
__device__ __forceinline__ void mma_tf32(float* c, const unsigned* a, const unsigned* b) {
    asm volatile(
        "mma.sync.aligned.m16n8k8.row.col.f32.tf32.tf32.f32 "
        "{%0,%1,%2,%3},{%4,%5,%6,%7},{%8,%9},{%0,%1,%2,%3};"
        : "+f"(c[0]), "+f"(c[1]), "+f"(c[2]), "+f"(c[3])
        : "r"(a[0]), "r"(a[1]), "r"(a[2]), "r"(a[3]), "r"(b[0]), "r"(b[1]));
}

__device__ __forceinline__ void load_edge(const int* __restrict__ ei, int e, int& s, int& d) {
    if (e >= NE) { s = d = e - NE; return; }
    if (g_ei64) { s = ei[2 * e]; d = ei[2 * (NE + e)]; }
    else        { s = ei[e];     d = ei[NE + e]; }
}

__global__ void detect_all(const unsigned* __restrict__ ei, const unsigned* __restrict__ m) {
    int lane = threadIdx.x;
    int f32 = 0, multi = 0;
    for (int i = lane; i < 2048; i += 32) {
        unsigned w = m[i];
        if (w == 0x3F800000u) f32 = 1;
        else if (w > 1u) multi = 1;
    }
    f32 = __any_sync(0xffffffffu, f32);
    multi = __any_sync(0xffffffffu, multi);
    if (lane == 0) {
        g_maskmode = f32 ? 2 : (multi ? 0 : 1);
        unsigned o = ei[1] | ei[3] | ei[5] | ei[7] | ei[9] | ei[11] | ei[13] | ei[15];
        g_ei64 = (o == 0u) ? 1 : 0;
    }
}

// ---------------- CSR construction ----------------
__global__ void zero_cnt() {
    int i = blockIdx.x * blockDim.x + threadIdx.x;
    if (i < NN) g_cnt[i] = 0;
}
__global__ void hist_kernel(const int* __restrict__ ei) {
    int e = blockIdx.x * blockDim.x + threadIdx.x;
    if (e >= EE) return;
    int s, d;
    load_edge(ei, e, s, d);
    atomicAdd(&g_cnt[d], 1);
}
__global__ void scan1() {
    __shared__ int sh[256];
    int t = threadIdx.x;
    int i = blockIdx.x * 256 + t;
    int v = (i < NN) ? g_cnt[i] : 0;
    sh[t] = v;
    __syncthreads();
#pragma unroll
    for (int off = 1; off < 256; off <<= 1) {
        int add = (t >= off) ? sh[t - off] : 0;
        __syncthreads();
        sh[t] += add;
        __syncthreads();
    }
    if (i < NN) g_off[i] = sh[t] - v;
    if (t == 255) g_bsum[blockIdx.x] = sh[255];
}
__global__ void scan2() {
    __shared__ int sh[256];
    int t = threadIdx.x;
    int v = (t < NB_SCAN) ? g_bsum[t] : 0;
    sh[t] = v;
    __syncthreads();
#pragma unroll
    for (int off = 1; off < 256; off <<= 1) {
        int add = (t >= off) ? sh[t - off] : 0;
        __syncthreads();
        sh[t] += add;
        __syncthreads();
    }
    if (t < NB_SCAN) g_bsumoff[t] = sh[t] - v;
}
__global__ void scan3() {
    int i = blockIdx.x * blockDim.x + threadIdx.x;
    if (i >= NN) return;
    int o = g_off[i] + g_bsumoff[i >> 8];
    g_off[i] = o;
    g_woff[i] = o;
}
__global__ void fill_kernel(const int* __restrict__ ei) {
    int e = blockIdx.x * blockDim.x + threadIdx.x;
    if (e >= EE) return;
    int s, d;
    load_edge(ei, e, s, d);
    int pos = atomicAdd(&g_woff[d], 1);
    g_csrc[pos] = s;
}

// ---------------- TF32 GEMM + fused attention-dot epilogue + bf16 store ----------------
// C[M,N] = A[M,K] @ B[K,N]; block tile 128x64; BN==64 == one attention head.
// Writes Cbf (bf16) and as_out/ad_out: as[n*S+bx] = sum_c C[n][bx*64+c]*att_s[bx*64+c].
__global__ void __launch_bounds__(256) gemm_att(const float* __restrict__ A,
                                                const float* __restrict__ B,
                                                __nv_bfloat16* __restrict__ Cbf,
                                                const float* __restrict__ att_s,
                                                const float* __restrict__ att_d,
                                                float* __restrict__ as_out,
                                                float* __restrict__ ad_out,
                                                int S, int M, int N, int K) {
    const int BM = 128, BK = 16;
    __shared__ float As[BK][BM + 4];
    __shared__ float Bs[BK][64 + 4];
    __shared__ float sAttS[64], sAttD[64];
    __shared__ float sRedS[2][128], sRedD[2][128];
    int tid = threadIdx.x;
    int bx = blockIdx.x;
    int bm = blockIdx.y * BM, bn = bx * 64;
    int wid = tid >> 5, lane = tid & 31;
    int wm = wid & 3, wn = wid >> 2;
    int g = lane >> 2, t = lane & 3;

    if (tid < 64) sAttS[tid] = att_s[bx * 64 + tid];
    else if (tid < 128) sAttD[tid - 64] = att_d[bx * 64 + tid - 64];

    float acc[2][4][4];
#pragma unroll
    for (int mf = 0; mf < 2; mf++)
#pragma unroll
        for (int nf = 0; nf < 4; nf++)
#pragma unroll
            for (int i = 0; i < 4; i++) acc[mf][nf][i] = 0.f;

    for (int k0 = 0; k0 < K; k0 += BK) {
#pragma unroll
        for (int i = 0; i < 2; i++) {
            int row = (tid >> 2) + i * 64;
            int c4 = (tid & 3) * 4;
            float4 v = make_float4(0.f, 0.f, 0.f, 0.f);
            if (bm + row < M)
                v = *(const float4*)&A[(size_t)(bm + row) * K + k0 + c4];
            As[c4 + 0][row] = v.x;
            As[c4 + 1][row] = v.y;
            As[c4 + 2][row] = v.z;
            As[c4 + 3][row] = v.w;
        }
        {
            int bRow = tid >> 4, bCol = (tid & 15) * 4;
            *(float4*)&Bs[bRow][bCol] = *(const float4*)&B[(size_t)(k0 + bRow) * N + bn + bCol];
        }
        __syncthreads();
#pragma unroll
        for (int k2 = 0; k2 < 2; k2++) {
            int kk = k2 * 8;
            unsigned aF[2][4], bF[4][2];
#pragma unroll
            for (int mf = 0; mf < 2; mf++) {
                int m0 = wm * 32 + mf * 16 + g;
                aF[mf][0] = f2tf(As[kk + t][m0]);
                aF[mf][1] = f2tf(As[kk + t][m0 + 8]);
                aF[mf][2] = f2tf(As[kk + t + 4][m0]);
                aF[mf][3] = f2tf(As[kk + t + 4][m0 + 8]);
            }
#pragma unroll
            for (int nf = 0; nf < 4; nf++) {
                int n0 = wn * 32 + nf * 8 + g;
                bF[nf][0] = f2tf(Bs[kk + t][n0]);
                bF[nf][1] = f2tf(Bs[kk + t + 4][n0]);
            }
#pragma unroll
            for (int mf = 0; mf < 2; mf++)
#pragma unroll
                for (int nf = 0; nf < 4; nf++)
                    mma_tf32(acc[mf][nf], aF[mf], bF[nf]);
        }
        __syncthreads();
    }

    // epilogue: bf16 store + per-row attention dots
    float psS[2][2] = {{0.f, 0.f}, {0.f, 0.f}};
    float psD[2][2] = {{0.f, 0.f}, {0.f, 0.f}};
#pragma unroll
    for (int mf = 0; mf < 2; mf++) {
#pragma unroll
        for (int nf = 0; nf < 4; nf++) {
            int colL = wn * 32 + nf * 8 + 2 * t;
            float aS0 = sAttS[colL], aS1 = sAttS[colL + 1];
            float aD0 = sAttD[colL], aD1 = sAttD[colL + 1];
            float* c = acc[mf][nf];
            psS[mf][0] += c[0] * aS0 + c[1] * aS1;
            psS[mf][1] += c[2] * aS0 + c[3] * aS1;
            psD[mf][0] += c[0] * aD0 + c[1] * aD1;
            psD[mf][1] += c[2] * aD0 + c[3] * aD1;
            int r = bm + wm * 32 + mf * 16 + g;
            __nv_bfloat162 p0 = __floats2bfloat162_rn(c[0], c[1]);
            __nv_bfloat162 p1 = __floats2bfloat162_rn(c[2], c[3]);
            if (r < M)     *(__nv_bfloat162*)&Cbf[(size_t)r * N + bn + colL] = p0;
            if (r + 8 < M) *(__nv_bfloat162*)&Cbf[(size_t)(r + 8) * N + bn + colL] = p1;
        }
    }
#pragma unroll
    for (int mf = 0; mf < 2; mf++)
#pragma unroll
        for (int ro = 0; ro < 2; ro++) {
            psS[mf][ro] += __shfl_xor_sync(0xffffffffu, psS[mf][ro], 1);
            psS[mf][ro] += __shfl_xor_sync(0xffffffffu, psS[mf][ro], 2);
            psD[mf][ro] += __shfl_xor_sync(0xffffffffu, psD[mf][ro], 1);
            psD[mf][ro] += __shfl_xor_sync(0xffffffffu, psD[mf][ro], 2);
        }
    if (t == 0) {
#pragma unroll
        for (int mf = 0; mf < 2; mf++)
#pragma unroll
            for (int ro = 0; ro < 2; ro++) {
                int rl = wm * 32 + mf * 16 + ro * 8 + g;
                sRedS[wn][rl] = psS[mf][ro];
                sRedD[wn][rl] = psD[mf][ro];
            }
    }
    __syncthreads();
    if (tid < 128 && bm + tid < M) {
        as_out[(size_t)(bm + tid) * S + bx] = sRedS[0][tid] + sRedS[1][tid];
        ad_out[(size_t)(bm + tid) * S + bx] = sRedD[0][tid] + sRedD[1][tid];
    }
}

// ---------------- layer 1 gather: warp per dst node ----------------
__global__ void __launch_bounds__(256) node1_kernel(const float* __restrict__ b1) {
    __shared__ float s_ex[8][CAP * 4];
    __shared__ int   s_src[8][CAP];
    int w = (blockIdx.x * blockDim.x + threadIdx.x) >> 5;
    int lane = threadIdx.x & 31;
    int wl = threadIdx.x >> 5;
    if (w >= NN) return;
    int base = g_off[w];
    int deg  = g_cnt[w];
    float4 ad = *(const float4*)(g_ad1 + (size_t)w * 4);

    float4 mx = make_float4(-3.4e38f, -3.4e38f, -3.4e38f, -3.4e38f);
    for (int j = lane; j < deg; j += 32) {
        int s = g_csrc[base + j];
        float4 as = *(const float4*)(g_as1 + (size_t)s * 4);
        float4 e;
        e.x = lrelu(as.x + ad.x); e.y = lrelu(as.y + ad.y);
        e.z = lrelu(as.z + ad.z); e.w = lrelu(as.w + ad.w);
        if (j < CAP) {
            s_src[wl][j] = s;
            *(float4*)&s_ex[wl][j * 4] = e;
        }
        mx.x = fmaxf(mx.x, e.x); mx.y = fmaxf(mx.y, e.y);
        mx.z = fmaxf(mx.z, e.z); mx.w = fmaxf(mx.w, e.w);
    }
    mx.x = warp_max(mx.x); mx.y = warp_max(mx.y);
    mx.z = warp_max(mx.z); mx.w = warp_max(mx.w);
    __syncwarp();

    float4 den = make_float4(0.f, 0.f, 0.f, 0.f);
    for (int j = lane; j < deg; j += 32) {
        float4 e;
        if (j < CAP) e = *(const float4*)&s_ex[wl][j * 4];
        else {
            int s = g_csrc[base + j];
            float4 as = *(const float4*)(g_as1 + (size_t)s * 4);
            e.x = lrelu(as.x + ad.x); e.y = lrelu(as.y + ad.y);
            e.z = lrelu(as.z + ad.z); e.w = lrelu(as.w + ad.w);
        }
        float4 ex;
        ex.x = __expf(e.x - mx.x); ex.y = __expf(e.y - mx.y);
        ex.z = __expf(e.z - mx.z); ex.w = __expf(e.w - mx.w);
        if (j < CAP) *(float4*)&s_ex[wl][j * 4] = ex;
        den.x += ex.x; den.y += ex.y; den.z += ex.z; den.w += ex.w;
    }
    den.x = warp_sum(den.x); den.y = warp_sum(den.y);
    den.z = warp_sum(den.z); den.w = warp_sum(den.w);
    __syncwarp();

    int head = lane >> 3;
    float mh  = head == 0 ? mx.x : head == 1 ? mx.y : head == 2 ? mx.z : mx.w;
    float adh = head == 0 ? ad.x : head == 1 ? ad.y : head == 2 ? ad.z : ad.w;
    float dh  = head == 0 ? den.x : head == 1 ? den.y : head == 2 ? den.z : den.w;
    float acc[8];
#pragma unroll
    for (int i = 0; i < 8; i++) acc[i] = 0.f;

    if (deg <= CAP) {
#pragma unroll 2
        for (int j = 0; j < deg; j++) {
            int s = s_src[wl][j];
            float ex = s_ex[wl][j * 4 + head];
            uint4 r = *(const uint4*)(g_h1bf + (size_t)s * HC + lane * 8);
            float2 f0 = __bfloat1622float2(*(const __nv_bfloat162*)&r.x);
            float2 f1 = __bfloat1622float2(*(const __nv_bfloat162*)&r.y);
            float2 f2 = __bfloat1622float2(*(const __nv_bfloat162*)&r.z);
            float2 f3 = __bfloat1622float2(*(const __nv_bfloat162*)&r.w);
            acc[0] += ex * f0.x; acc[1] += ex * f0.y;
            acc[2] += ex * f1.x; acc[3] += ex * f1.y;
            acc[4] += ex * f2.x; acc[5] += ex * f2.y;
            acc[6] += ex * f3.x; acc[7] += ex * f3.y;
        }
    } else {
        for (int j = 0; j < deg; j++) {
            int s; float ex;
            if (j < CAP) {
                s = s_src[wl][j];
                ex = s_ex[wl][j * 4 + head];
            } else {
                s = g_csrc[base + j];
                ex = __expf(lrelu(g_as1[(size_t)s * 4 + head] + adh) - mh);
            }
            uint4 r = *(const uint4*)(g_h1bf + (size_t)s * HC + lane * 8);
            float2 f0 = __bfloat1622float2(*(const __nv_bfloat162*)&r.x);
            float2 f1 = __bfloat1622float2(*(const __nv_bfloat162*)&r.y);
            float2 f2 = __bfloat1622float2(*(const __nv_bfloat162*)&r.z);
            float2 f3 = __bfloat1622float2(*(const __nv_bfloat162*)&r.w);
            acc[0] += ex * f0.x; acc[1] += ex * f0.y;
            acc[2] += ex * f1.x; acc[3] += ex * f1.y;
            acc[4] += ex * f2.x; acc[5] += ex * f2.y;
            acc[6] += ex * f3.x; acc[7] += ex * f3.y;
        }
    }
    float inv = 1.f / dh;
    int f = lane * 8;
    const float4* bp = (const float4*)(b1 + f);
    float4 bb0 = bp[0], bb1 = bp[1];
    float4 o0, o1;
    o0.x = fmaxf(acc[0] * inv + bb0.x, 0.f);
    o0.y = fmaxf(acc[1] * inv + bb0.y, 0.f);
    o0.z = fmaxf(acc[2] * inv + bb0.z, 0.f);
    o0.w = fmaxf(acc[3] * inv + bb0.w, 0.f);
    o1.x = fmaxf(acc[4] * inv + bb1.x, 0.f);
    o1.y = fmaxf(acc[5] * inv + bb1.y, 0.f);
    o1.z = fmaxf(acc[6] * inv + bb1.z, 0.f);
    o1.w = fmaxf(acc[7] * inv + bb1.w, 0.f);
    float4* op = (float4*)(g_h1 + (size_t)w * HC + f);
    op[0] = o0;
    op[1] = o1;
}

// ---------------- layer 2 gather + node scores ----------------
__global__ void __launch_bounds__(256) node2_kernel(const float* __restrict__ b2,
                                                    const float* __restrict__ aw,
                                                    const float* __restrict__ ab) {
    __shared__ float s_ex[8][CAP];
    __shared__ int   s_src[8][CAP];
    int w = (blockIdx.x * blockDim.x + threadIdx.x) >> 5;
    int lane = threadIdx.x & 31;
    int wl = threadIdx.x >> 5;
    if (w >= NN) return;
    int base = g_off[w];
    int deg  = g_cnt[w];
    float ad = g_ad2[w];

    float mx = -3.4e38f;
    for (int j = lane; j < deg; j += 32) {
        int s = g_csrc[base + j];
        float e = lrelu(g_as2[s] + ad);
        if (j < CAP) { s_src[wl][j] = s; s_ex[wl][j] = e; }
        mx = fmaxf(mx, e);
    }
    mx = warp_max(mx);
    __syncwarp();

    float den = 0.f;
    for (int j = lane; j < deg; j += 32) {
        float e = (j < CAP) ? s_ex[wl][j]
                            : lrelu(g_as2[g_csrc[base + j]] + ad);
        float ex = __expf(e - mx);
        if (j < CAP) s_ex[wl][j] = ex;
        den += ex;
    }
    den = warp_sum(den);
    __syncwarp();

    float acc0 = 0.f, acc1 = 0.f;
    if (deg <= CAP) {
#pragma unroll 2
        for (int j = 0; j < deg; j++) {
            int s = s_src[wl][j];
            float ex = s_ex[wl][j];
            __nv_bfloat162 vb = *(const __nv_bfloat162*)(g_h2bf + (size_t)s * HID + lane * 2);
            float2 v = __bfloat1622float2(vb);
            acc0 += ex * v.x;
            acc1 += ex * v.y;
        }
    } else {
        for (int j = 0; j < deg; j++) {
            int s; float ex;
            if (j < CAP) { s = s_src[wl][j]; ex = s_ex[wl][j]; }
            else {
                s = g_csrc[base + j];
                ex = __expf(lrelu(g_as2[s] + ad) - mx);
            }
            __nv_bfloat162 vb = *(const __nv_bfloat162*)(g_h2bf + (size_t)s * HID + lane * 2);
            float2 v = __bfloat1622float2(vb);
            acc0 += ex * v.x;
            acc1 += ex * v.y;
        }
    }
    float inv = 1.f / den;
    int c = lane * 2;
    float h0 = acc0 * inv + b2[c];
    float h1 = acc1 * inv + b2[c + 1];
    *(float2*)(g_h2 + (size_t)w * HID + c) = make_float2(h0, h1);
    float sc = warp_sum(h0 * aw[c] + h1 * aw[c + 1]);
    if (lane == 0) g_scores[w] = tanhf(sc + ab[0]);
}

// ---------------- per-graph pooled stop score ----------------
__global__ void context_kernel(const int* __restrict__ cn, const int* __restrict__ cc,
                               const float* __restrict__ sw, const float* __restrict__ sb) {
    int g = blockIdx.x;
    int c = threadIdx.x;   // 64 threads
    int cnt = cc[g];
    float sum = 0.f;
#pragma unroll
    for (int k = 0; k < KMAX; k++) {
        if (k < cnt) {
            int n = cn[g * KMAX + k];
            sum += g_h2[(size_t)n * HID + c];
        }
    }
    int cm = cnt > 1 ? cnt : 1;
    float ctx = sum / (float)cm;
    __shared__ float red[64];
    red[c] = ctx * sw[c];
    __syncthreads();
    for (int o = 32; o; o >>= 1) {
        if (c < o) red[c] += red[c + o];
        __syncthreads();
    }
    if (c == 0) g_stop[g] = tanhf(red[0] + sb[0]);
}

__device__ __forceinline__ bool get_mask(const void* masks, int mode, int g, int i) {
    if (mode == 2) return ((const float*)masks)[(size_t)g * NN + i] != 0.f;
    if (mode == 1) return ((const int*)masks)[(size_t)g * NN + i] != 0;
    return ((const unsigned char*)masks)[(size_t)g * NN + i] != 0;
}

// ---------------- split softmax ----------------
__global__ void __launch_bounds__(256) softmaxA(const void* __restrict__ masks) {
    int g = blockIdx.x >> 3, ch = blockIdx.x & 7;
    int tid = threadIdx.x;
    int i0 = ch * CHUNK;
    int mode = g_maskmode;
    __shared__ float sm[8];

    float mx = -3.4e38f;
    for (int i = tid; i < CHUNK; i += 256) {
        int idx = i0 + i;
        float s = get_mask(masks, mode, g, idx) ? g_scores[idx] : -1e9f;
        mx = fmaxf(mx, s);
    }
    mx = warp_max(mx);
    if ((tid & 31) == 0) sm[tid >> 5] = mx;
    __syncthreads();
    if (tid < 32) {
        float v = (tid < 8) ? sm[tid] : -3.4e38f;
        v = warp_max(v);
        if (tid == 0) sm[0] = v;
    }
    __syncthreads();
    mx = sm[0];
    __syncthreads();

    float sum = 0.f;
    for (int i = tid; i < CHUNK; i += 256) {
        int idx = i0 + i;
        float s = get_mask(masks, mode, g, idx) ? g_scores[idx] : -1e9f;
        sum += __expf(s - mx);
    }
    sum = warp_sum(sum);
    if ((tid & 31) == 0) sm[tid >> 5] = sum;
    __syncthreads();
    if (tid < 32) {
        float v = (tid < 8) ? sm[tid] : 0.f;
        v = warp_sum(v);
        if (tid == 0) {
            g_pm[g * SCH + ch] = mx;
            g_ps[g * SCH + ch] = v;
        }
    }
}

__global__ void softmaxB(const int* __restrict__ cc, float* __restrict__ out) {
    int g = blockIdx.x;
    int lane = threadIdx.x;
    float m = (lane < SCH) ? g_pm[g * SCH + lane] : -3.4e38f;
    float M = warp_max(m);
    float stop = g_stop[g];
    M = fmaxf(M, stop);
    float s = (lane < SCH) ? g_ps[g * SCH + lane] * __expf(m - M) : 0.f;
    float Ssum = warp_sum(s) + __expf(stop - M);
    if (lane == 0) {
        g_smx[g] = M;
        float inv = 1.f / Ssum;
        g_sinv[g] = inv;
        out[(size_t)g * NP1 + NN] = (cc[g] == 0) ? 1.f : __expf(stop - M) * inv;
    }
}

__global__ void __launch_bounds__(256) softmaxC(const void* __restrict__ masks,
                                                const int* __restrict__ cc,
                                                float* __restrict__ out) {
    int g = blockIdx.x >> 3, ch = blockIdx.x & 7;
    int tid = threadIdx.x;
    int i0 = ch * CHUNK;
    int mode = g_maskmode;
    float* o = out + (size_t)g * NP1;
    if (cc[g] == 0) {
        for (int i = tid; i < CHUNK; i += 256) o[i0 + i] = 0.f;
        return;
    }
    float mx = g_smx[g], inv = g_sinv[g];
    for (int i = tid; i < CHUNK; i += 256) {
        int idx = i0 + i;
        float s = get_mask(masks, mode, g, idx) ? g_scores[idx] : -1e9f;
        o[idx] = __expf(s - mx) * inv;
    }
}

// ---------------- host ----------------
extern "C" void kernel_launch(void* const* d_in, const int* in_sizes, int n_in,
                              void* d_out, int out_size) {
    const float* x    = (const float*)d_in[0];
    const int*   ei   = (const int*)d_in[1];
    const int*   cn   = (const int*)d_in[2];
    const int*   cc   = (const int*)d_in[3];
    const void*  masks = d_in[4];
    const float* W1   = (const float*)d_in[5];
    const float* as1w = (const float*)d_in[6];
    const float* ad1w = (const float*)d_in[7];
    const float* b1   = (const float*)d_in[8];
    const float* W2   = (const float*)d_in[9];
    const float* as2w = (const float*)d_in[10];
    const float* ad2w = (const float*)d_in[11];
    const float* b2   = (const float*)d_in[12];
    const float* aw   = (const float*)d_in[13];
    const float* ab   = (const float*)d_in[14];
    const float* sw   = (const float*)d_in[15];
    const float* sb   = (const float*)d_in[16];
    float* out = (float*)d_out;

    __nv_bfloat16 *h1bf_p, *h2bf_p;
    float *h1_p, *as1_p, *ad1_p, *as2_p, *ad2_p;
    cudaGetSymbolAddress((void**)&h1bf_p, g_h1bf);
    cudaGetSymbolAddress((void**)&h1_p, g_h1);
    cudaGetSymbolAddress((void**)&h2bf_p, g_h2bf);
    cudaGetSymbolAddress((void**)&as1_p, g_as1);
    cudaGetSymbolAddress((void**)&ad1_p, g_ad1);
    cudaGetSymbolAddress((void**)&as2_p, g_as2);
    cudaGetSymbolAddress((void**)&ad2_p, g_ad2);

    static cudaStream_t s2 = nullptr;
    static cudaEvent_t evFork = nullptr, evJoin = nullptr;
    if (!s2) {
        cudaStreamCreateWithFlags(&s2, cudaStreamNonBlocking);
        cudaEventCreateWithFlags(&evFork, cudaEventDisableTiming);
        cudaEventCreateWithFlags(&evJoin, cudaEventDisableTiming);
    }

    // fork: detect + CSR build on s2; GEMM1 (independent) on main
    cudaEventRecord(evFork, 0);
    cudaStreamWaitEvent(s2, evFork, 0);
    detect_all<<<1, 32, 0, s2>>>((const unsigned*)ei, (const unsigned*)masks);
    zero_cnt<<<(NN + 255) / 256, 256, 0, s2>>>();
    hist_kernel<<<(EE + 255) / 256, 256, 0, s2>>>(ei);
    scan1<<<NB_SCAN, 256, 0, s2>>>();
    scan2<<<1, 256, 0, s2>>>();
    scan3<<<NB_SCAN, 256, 0, s2>>>();
    fill_kernel<<<(EE + 255) / 256, 256, 0, s2>>>(ei);
    cudaEventRecord(evJoin, s2);

    // layer 1 GEMM (+att dots + bf16 store fused)
    gemm_att<<<dim3(HEADS, (NN + 127) / 128), 256>>>(x, W1, h1bf_p, as1w, ad1w,
                                                     as1_p, ad1_p, HEADS, NN, HC, FIN);
    cudaStreamWaitEvent(0, evJoin, 0);
    node1_kernel<<<(NN + 7) / 8, 256>>>(b1);

    // layer 2
    gemm_att<<<dim3(1, (NN + 127) / 128), 256>>>(h1_p, W2, h2bf_p, as2w, ad2w,
                                                 as2_p, ad2_p, 1, NN, HID, HC);
    node2_kernel<<<(NN + 7) / 8, 256>>>(b2, aw, ab);

    // heads
    context_kernel<<<NG, 64>>>(cn, cc, sw, sb);
    softmaxA<<<NG * SCH, 256>>>(masks);
    softmaxB<<<NG, 32>>>(cc, out);
    softmaxC<<<NG * SCH, 256>>>(masks, cc, out);
}

// round 11
// speedup vs baseline: 7.2051x; 1.0552x over previous
#include <cuda_runtime.h>
#include <cuda_bf16.h>
#include <cuda_fp16.h>

#define NN 50000
#define NE 800000
#define EE (NE + NN)
#define NG 32
#define KMAX 16
#define FIN 128
#define HID 64
#define HEADS 4
#define HC 256          // HEADS*HID
#define NP1 (NN + 1)
#define CAP 160
#define NB_SCAN ((NN + 255) / 256)
#define SCH 8
#define CHUNK (NN / SCH)   // 6250

// ---------------- scratch ----------------
__device__ unsigned char g_h1f8[NN * HC];    // x@W1 in fp8 e4m3 (gather operand)
__device__ float         g_h1  [NN * HC];    // after GAT1 + relu (GEMM2 input)
__device__ __nv_bfloat16 g_h2bf[NN * HID];   // h1@W2 in bf16 (gather operand)
__device__ float         g_h2  [NN * HID];   // after GAT2 (+b2)
__device__ float         g_as1 [NN * HEADS];
__device__ float         g_ad1 [NN * HEADS];
__device__ float         g_as2 [NN];
__device__ float         g_ad2 [NN];
__device__ float         g_scores[NN];
__device__ float         g_stop  [NG];
__device__ int           g_ei64;
__device__ int           g_maskmode;         // 0=uint8, 1=int32, 2=float32

// CSR scratch
__device__ int g_cnt [NN];
__device__ int g_off [NN];
__device__ int g_woff[NN];
__device__ int g_csrc[EE];
__device__ int g_bsum[NB_SCAN];
__device__ int g_bsumoff[NB_SCAN];

// softmax partials
__device__ float g_pm[NG * SCH];
__device__ float g_ps[NG * SCH];
__device__ float g_smx[NG];
__device__ float g_sinv[NG];

// ---------------- helpers ----------------
__device__ __forceinline__ float lrelu(float a) { return a > 0.f ? a : 0.2f * a; }

__device__ __forceinline__ float warp_sum(float v) {
#pragma unroll
    for (int o = 16; o; o >>= 1) v += __shfl_xor_sync(0xffffffffu, v, o);
    return v;
}
__device__ __forceinline__ float warp_max(float v) {
#pragma unroll
    for (int o = 16; o; o >>= 1) v = fmaxf(v, __shfl_xor_sync(0xffffffffu, v, o));
    return v;
}

__device__ __forceinline__ unsigned f2tf(float f) {
    unsigned u;
    asm("cvt.rna.tf32.f32 %0, %1;" : "=r"(u) : "f"(f));
    return u;
}
__device__ __forceinline__ void mma_tf32(float* c, const unsigned* a, const unsigned* b) {
    asm volatile(
        "mma.sync.aligned.m16n8k8.row.col.f32.tf32.tf32.f32 "
        "{%0,%1,%2,%3},{%4,%5,%6,%7},{%8,%9},{%0,%1,%2,%3};"
        : "+f"(c[0]), "+f"(c[1]), "+f"(c[2]), "+f"(c[3])
        : "r"(a[0]), "r"(a[1]), "r"(a[2]), "r"(a[3]), "r"(b[0]), "r"(b[1]));
}

// fp8 e4m3 pack: returns (fp8(hi)<<8)|fp8(lo) -> little-endian bytes [lo, hi]
__device__ __forceinline__ unsigned short f2_to_fp8x2(float hi, float lo) {
    unsigned short r;
    asm("cvt.rn.satfinite.e4m3x2.f32 %0, %1, %2;" : "=h"(r) : "f"(hi), "f"(lo));
    return r;
}
// fp8x2 (low 16 bits) -> half2, low fp8 -> .x
__device__ __forceinline__ __half2 fp8x2_to_h2(unsigned v) {
    unsigned r;
    unsigned short s = (unsigned short)v;
    asm("cvt.rn.f16x2.e4m3x2 %0, %1;" : "=r"(r) : "h"(s));
    return *(__half2*)&r;
}

__device__ __forceinline__ void load_edge(const int* __restrict__ ei, int e, int& s, int& d) {
    if (e >= NE) { s = d = e - NE; return; }
    if (g_ei64) { s = ei[2 * e]; d = ei[2 * (NE + e)]; }
    else        { s = ei[e];     d = ei[NE + e]; }
}

__global__ void detect_all(const unsigned* __restrict__ ei, const unsigned* __restrict__ m) {
    int lane = threadIdx.x;
    int f32 = 0, multi = 0;
    for (int i = lane; i < 2048; i += 32) {
        unsigned w = m[i];
        if (w == 0x3F800000u) f32 = 1;
        else if (w > 1u) multi = 1;
    }
    f32 = __any_sync(0xffffffffu, f32);
    multi = __any_sync(0xffffffffu, multi);
    if (lane == 0) {
        g_maskmode = f32 ? 2 : (multi ? 0 : 1);
        unsigned o = ei[1] | ei[3] | ei[5] | ei[7] | ei[9] | ei[11] | ei[13] | ei[15];
        g_ei64 = (o == 0u) ? 1 : 0;
    }
}

// ---------------- CSR construction ----------------
__global__ void zero_cnt() {
    int i = blockIdx.x * blockDim.x + threadIdx.x;
    if (i < NN) g_cnt[i] = 0;
}
__global__ void hist_kernel(const int* __restrict__ ei) {
    int e = blockIdx.x * blockDim.x + threadIdx.x;
    if (e >= EE) return;
    int s, d;
    load_edge(ei, e, s, d);
    atomicAdd(&g_cnt[d], 1);
}
__global__ void scan1() {
    __shared__ int sh[256];
    int t = threadIdx.x;
    int i = blockIdx.x * 256 + t;
    int v = (i < NN) ? g_cnt[i] : 0;
    sh[t] = v;
    __syncthreads();
#pragma unroll
    for (int off = 1; off < 256; off <<= 1) {
        int add = (t >= off) ? sh[t - off] : 0;
        __syncthreads();
        sh[t] += add;
        __syncthreads();
    }
    if (i < NN) g_off[i] = sh[t] - v;
    if (t == 255) g_bsum[blockIdx.x] = sh[255];
}
__global__ void scan2() {
    __shared__ int sh[256];
    int t = threadIdx.x;
    int v = (t < NB_SCAN) ? g_bsum[t] : 0;
    sh[t] = v;
    __syncthreads();
#pragma unroll
    for (int off = 1; off < 256; off <<= 1) {
        int add = (t >= off) ? sh[t - off] : 0;
        __syncthreads();
        sh[t] += add;
        __syncthreads();
    }
    if (t < NB_SCAN) g_bsumoff[t] = sh[t] - v;
}
__global__ void scan3() {
    int i = blockIdx.x * blockDim.x + threadIdx.x;
    if (i >= NN) return;
    int o = g_off[i] + g_bsumoff[i >> 8];
    g_off[i] = o;
    g_woff[i] = o;
}
__global__ void fill_kernel(const int* __restrict__ ei) {
    int e = blockIdx.x * blockDim.x + threadIdx.x;
    if (e >= EE) return;
    int s, d;
    load_edge(ei, e, s, d);
    int pos = atomicAdd(&g_woff[d], 1);
    g_csrc[pos] = s;
}

// ---------------- TF32 GEMM + fused attention-dot epilogue + fp8/bf16 store ----------------
template <int STORE_FP8>
__global__ void __launch_bounds__(256) gemm_att(const float* __restrict__ A,
                                                const float* __restrict__ B,
                                                void* __restrict__ Cout,
                                                const float* __restrict__ att_s,
                                                const float* __restrict__ att_d,
                                                float* __restrict__ as_out,
                                                float* __restrict__ ad_out,
                                                int S, int M, int N, int K) {
    const int BM = 128, BK = 16;
    __shared__ float As[BK][BM + 4];
    __shared__ float Bs[BK][64 + 4];
    __shared__ float sAttS[64], sAttD[64];
    __shared__ float sRedS[2][128], sRedD[2][128];
    int tid = threadIdx.x;
    int bx = blockIdx.x;
    int bm = blockIdx.y * BM, bn = bx * 64;
    int wid = tid >> 5, lane = tid & 31;
    int wm = wid & 3, wn = wid >> 2;
    int g = lane >> 2, t = lane & 3;

    if (tid < 64) sAttS[tid] = att_s[bx * 64 + tid];
    else if (tid < 128) sAttD[tid - 64] = att_d[bx * 64 + tid - 64];

    float acc[2][4][4];
#pragma unroll
    for (int mf = 0; mf < 2; mf++)
#pragma unroll
        for (int nf = 0; nf < 4; nf++)
#pragma unroll
            for (int i = 0; i < 4; i++) acc[mf][nf][i] = 0.f;

    for (int k0 = 0; k0 < K; k0 += BK) {
#pragma unroll
        for (int i = 0; i < 2; i++) {
            int row = (tid >> 2) + i * 64;
            int c4 = (tid & 3) * 4;
            float4 v = make_float4(0.f, 0.f, 0.f, 0.f);
            if (bm + row < M)
                v = *(const float4*)&A[(size_t)(bm + row) * K + k0 + c4];
            As[c4 + 0][row] = v.x;
            As[c4 + 1][row] = v.y;
            As[c4 + 2][row] = v.z;
            As[c4 + 3][row] = v.w;
        }
        {
            int bRow = tid >> 4, bCol = (tid & 15) * 4;
            *(float4*)&Bs[bRow][bCol] = *(const float4*)&B[(size_t)(k0 + bRow) * N + bn + bCol];
        }
        __syncthreads();
#pragma unroll
        for (int k2 = 0; k2 < 2; k2++) {
            int kk = k2 * 8;
            unsigned aF[2][4], bF[4][2];
#pragma unroll
            for (int mf = 0; mf < 2; mf++) {
                int m0 = wm * 32 + mf * 16 + g;
                aF[mf][0] = f2tf(As[kk + t][m0]);
                aF[mf][1] = f2tf(As[kk + t][m0 + 8]);
                aF[mf][2] = f2tf(As[kk + t + 4][m0]);
                aF[mf][3] = f2tf(As[kk + t + 4][m0 + 8]);
            }
#pragma unroll
            for (int nf = 0; nf < 4; nf++) {
                int n0 = wn * 32 + nf * 8 + g;
                bF[nf][0] = f2tf(Bs[kk + t][n0]);
                bF[nf][1] = f2tf(Bs[kk + t + 4][n0]);
            }
#pragma unroll
            for (int mf = 0; mf < 2; mf++)
#pragma unroll
                for (int nf = 0; nf < 4; nf++)
                    mma_tf32(acc[mf][nf], aF[mf], bF[nf]);
        }
        __syncthreads();
    }

    // epilogue: quantized store + per-row attention dots
    float psS[2][2] = {{0.f, 0.f}, {0.f, 0.f}};
    float psD[2][2] = {{0.f, 0.f}, {0.f, 0.f}};
#pragma unroll
    for (int mf = 0; mf < 2; mf++) {
#pragma unroll
        for (int nf = 0; nf < 4; nf++) {
            int colL = wn * 32 + nf * 8 + 2 * t;
            float aS0 = sAttS[colL], aS1 = sAttS[colL + 1];
            float aD0 = sAttD[colL], aD1 = sAttD[colL + 1];
            float* c = acc[mf][nf];
            psS[mf][0] += c[0] * aS0 + c[1] * aS1;
            psS[mf][1] += c[2] * aS0 + c[3] * aS1;
            psD[mf][0] += c[0] * aD0 + c[1] * aD1;
            psD[mf][1] += c[2] * aD0 + c[3] * aD1;
            int r = bm + wm * 32 + mf * 16 + g;
            if (STORE_FP8) {
                unsigned char* Cf8 = (unsigned char*)Cout;
                unsigned short p0 = f2_to_fp8x2(c[1], c[0]);
                unsigned short p1 = f2_to_fp8x2(c[3], c[2]);
                if (r < M)     *(unsigned short*)&Cf8[(size_t)r * N + bn + colL] = p0;
                if (r + 8 < M) *(unsigned short*)&Cf8[(size_t)(r + 8) * N + bn + colL] = p1;
            } else {
                __nv_bfloat16* Cbf = (__nv_bfloat16*)Cout;
                __nv_bfloat162 p0 = __floats2bfloat162_rn(c[0], c[1]);
                __nv_bfloat162 p1 = __floats2bfloat162_rn(c[2], c[3]);
                if (r < M)     *(__nv_bfloat162*)&Cbf[(size_t)r * N + bn + colL] = p0;
                if (r + 8 < M) *(__nv_bfloat162*)&Cbf[(size_t)(r + 8) * N + bn + colL] = p1;
            }
        }
    }
#pragma unroll
    for (int mf = 0; mf < 2; mf++)
#pragma unroll
        for (int ro = 0; ro < 2; ro++) {
            psS[mf][ro] += __shfl_xor_sync(0xffffffffu, psS[mf][ro], 1);
            psS[mf][ro] += __shfl_xor_sync(0xffffffffu, psS[mf][ro], 2);
            psD[mf][ro] += __shfl_xor_sync(0xffffffffu, psD[mf][ro], 1);
            psD[mf][ro] += __shfl_xor_sync(0xffffffffu, psD[mf][ro], 2);
        }
    if (t == 0) {
#pragma unroll
        for (int mf = 0; mf < 2; mf++)
#pragma unroll
            for (int ro = 0; ro < 2; ro++) {
                int rl = wm * 32 + mf * 16 + ro * 8 + g;
                sRedS[wn][rl] = psS[mf][ro];
                sRedD[wn][rl] = psD[mf][ro];
            }
    }
    __syncthreads();
    if (tid < 128 && bm + tid < M) {
        as_out[(size_t)(bm + tid) * S + bx] = sRedS[0][tid] + sRedS[1][tid];
        ad_out[(size_t)(bm + tid) * S + bx] = sRedD[0][tid] + sRedD[1][tid];
    }
}

// ---------------- layer 1 gather: warp per dst node (no-max softmax, fp8 rows) ----------------
__global__ void __launch_bounds__(256) node1_kernel(const float* __restrict__ b1) {
    __shared__ float s_ex[8][CAP * 4];
    __shared__ int   s_src[8][CAP];
    int w = (blockIdx.x * blockDim.x + threadIdx.x) >> 5;
    int lane = threadIdx.x & 31;
    int wl = threadIdx.x >> 5;
    if (w >= NN) return;
    int base = g_off[w];
    int deg  = g_cnt[w];
    float4 ad = *(const float4*)(g_ad1 + (size_t)w * 4);

    // pass A: ex = exp(lrelu(as+ad)) per head; cache; accumulate denominator
    float4 den = make_float4(0.f, 0.f, 0.f, 0.f);
    for (int j = lane; j < deg; j += 32) {
        int s = g_csrc[base + j];
        float4 as = *(const float4*)(g_as1 + (size_t)s * 4);
        float4 ex;
        ex.x = __expf(lrelu(as.x + ad.x));
        ex.y = __expf(lrelu(as.y + ad.y));
        ex.z = __expf(lrelu(as.z + ad.z));
        ex.w = __expf(lrelu(as.w + ad.w));
        if (j < CAP) {
            s_src[wl][j] = s;
            *(float4*)&s_ex[wl][j * 4] = ex;
        }
        den.x += ex.x; den.y += ex.y; den.z += ex.z; den.w += ex.w;
    }
    den.x = warp_sum(den.x); den.y = warp_sum(den.y);
    den.z = warp_sum(den.z); den.w = warp_sum(den.w);
    __syncwarp();

    // pass B: feature accumulation in f16x2 (lane owns 8 features, head = lane/8)
    int head = lane >> 3;
    float adh = head == 0 ? ad.x : head == 1 ? ad.y : head == 2 ? ad.z : ad.w;
    float dh  = head == 0 ? den.x : head == 1 ? den.y : head == 2 ? den.z : den.w;
    __half2 hz = __float2half2_rn(0.f);
    __half2 hacc0 = hz, hacc1 = hz, hacc2 = hz, hacc3 = hz;

    if (deg <= CAP) {
#pragma unroll 2
        for (int j = 0; j < deg; j++) {
            int s = s_src[wl][j];
            float ex = s_ex[wl][j * 4 + head];
            uint2 r = *(const uint2*)(g_h1f8 + (size_t)s * HC + lane * 8);
            __half2 exh = __float2half2_rn(ex);
            hacc0 = __hfma2(exh, fp8x2_to_h2(r.x), hacc0);
            hacc1 = __hfma2(exh, fp8x2_to_h2(r.x >> 16), hacc1);
            hacc2 = __hfma2(exh, fp8x2_to_h2(r.y), hacc2);
            hacc3 = __hfma2(exh, fp8x2_to_h2(r.y >> 16), hacc3);
        }
    } else {
        for (int j = 0; j < deg; j++) {
            int s; float ex;
            if (j < CAP) {
                s = s_src[wl][j];
                ex = s_ex[wl][j * 4 + head];
            } else {
                s = g_csrc[base + j];
                ex = __expf(lrelu(g_as1[(size_t)s * 4 + head] + adh));
            }
            uint2 r = *(const uint2*)(g_h1f8 + (size_t)s * HC + lane * 8);
            __half2 exh = __float2half2_rn(ex);
            hacc0 = __hfma2(exh, fp8x2_to_h2(r.x), hacc0);
            hacc1 = __hfma2(exh, fp8x2_to_h2(r.x >> 16), hacc1);
            hacc2 = __hfma2(exh, fp8x2_to_h2(r.y), hacc2);
            hacc3 = __hfma2(exh, fp8x2_to_h2(r.y >> 16), hacc3);
        }
    }
    float inv = 1.f / dh;
    float2 a0 = __half22float2(hacc0);
    float2 a1 = __half22float2(hacc1);
    float2 a2 = __half22float2(hacc2);
    float2 a3 = __half22float2(hacc3);
    int f = lane * 8;
    const float4* bp = (const float4*)(b1 + f);
    float4 bb0 = bp[0], bb1 = bp[1];
    float4 o0, o1;
    o0.x = fmaxf(a0.x * inv + bb0.x, 0.f);
    o0.y = fmaxf(a0.y * inv + bb0.y, 0.f);
    o0.z = fmaxf(a1.x * inv + bb0.z, 0.f);
    o0.w = fmaxf(a1.y * inv + bb0.w, 0.f);
    o1.x = fmaxf(a2.x * inv + bb1.x, 0.f);
    o1.y = fmaxf(a2.y * inv + bb1.y, 0.f);
    o1.z = fmaxf(a3.x * inv + bb1.z, 0.f);
    o1.w = fmaxf(a3.y * inv + bb1.w, 0.f);
    float4* op = (float4*)(g_h1 + (size_t)w * HC + f);
    op[0] = o0;
    op[1] = o1;
}

// ---------------- layer 2 gather + node scores (no-max softmax) ----------------
__global__ void __launch_bounds__(256) node2_kernel(const float* __restrict__ b2,
                                                    const float* __restrict__ aw,
                                                    const float* __restrict__ ab) {
    __shared__ float s_ex[8][CAP];
    __shared__ int   s_src[8][CAP];
    int w = (blockIdx.x * blockDim.x + threadIdx.x) >> 5;
    int lane = threadIdx.x & 31;
    int wl = threadIdx.x >> 5;
    if (w >= NN) return;
    int base = g_off[w];
    int deg  = g_cnt[w];
    float ad = g_ad2[w];

    float den = 0.f;
    for (int j = lane; j < deg; j += 32) {
        int s = g_csrc[base + j];
        float ex = __expf(lrelu(g_as2[s] + ad));
        if (j < CAP) { s_src[wl][j] = s; s_ex[wl][j] = ex; }
        den += ex;
    }
    den = warp_sum(den);
    __syncwarp();

    float acc0 = 0.f, acc1 = 0.f;
    if (deg <= CAP) {
#pragma unroll 2
        for (int j = 0; j < deg; j++) {
            int s = s_src[wl][j];
            float ex = s_ex[wl][j];
            __nv_bfloat162 vb = *(const __nv_bfloat162*)(g_h2bf + (size_t)s * HID + lane * 2);
            float2 v = __bfloat1622float2(vb);
            acc0 += ex * v.x;
            acc1 += ex * v.y;
        }
    } else {
        for (int j = 0; j < deg; j++) {
            int s; float ex;
            if (j < CAP) { s = s_src[wl][j]; ex = s_ex[wl][j]; }
            else {
                s = g_csrc[base + j];
                ex = __expf(lrelu(g_as2[s] + ad));
            }
            __nv_bfloat162 vb = *(const __nv_bfloat162*)(g_h2bf + (size_t)s * HID + lane * 2);
            float2 v = __bfloat1622float2(vb);
            acc0 += ex * v.x;
            acc1 += ex * v.y;
        }
    }
    float inv = 1.f / den;
    int c = lane * 2;
    float h0 = acc0 * inv + b2[c];
    float h1 = acc1 * inv + b2[c + 1];
    *(float2*)(g_h2 + (size_t)w * HID + c) = make_float2(h0, h1);
    float sc = warp_sum(h0 * aw[c] + h1 * aw[c + 1]);
    if (lane == 0) g_scores[w] = tanhf(sc + ab[0]);
}

// ---------------- per-graph pooled stop score ----------------
__global__ void context_kernel(const int* __restrict__ cn, const int* __restrict__ cc,
                               const float* __restrict__ sw, const float* __restrict__ sb) {
    int g = blockIdx.x;
    int c = threadIdx.x;   // 64 threads
    int cnt = cc[g];
    float sum = 0.f;
#pragma unroll
    for (int k = 0; k < KMAX; k++) {
        if (k < cnt) {
            int n = cn[g * KMAX + k];
            sum += g_h2[(size_t)n * HID + c];
        }
    }
    int cm = cnt > 1 ? cnt : 1;
    float ctx = sum / (float)cm;
    __shared__ float red[64];
    red[c] = ctx * sw[c];
    __syncthreads();
    for (int o = 32; o; o >>= 1) {
        if (c < o) red[c] += red[c + o];
        __syncthreads();
    }
    if (c == 0) g_stop[g] = tanhf(red[0] + sb[0]);
}

__device__ __forceinline__ bool get_mask(const void* masks, int mode, int g, int i) {
    if (mode == 2) return ((const float*)masks)[(size_t)g * NN + i] != 0.f;
    if (mode == 1) return ((const int*)masks)[(size_t)g * NN + i] != 0;
    return ((const unsigned char*)masks)[(size_t)g * NN + i] != 0;
}

// ---------------- split softmax ----------------
__global__ void __launch_bounds__(256) softmaxA(const void* __restrict__ masks) {
    int g = blockIdx.x >> 3, ch = blockIdx.x & 7;
    int tid = threadIdx.x;
    int i0 = ch * CHUNK;
    int mode = g_maskmode;
    __shared__ float sm[8];

    float mx = -3.4e38f;
    for (int i = tid; i < CHUNK; i += 256) {
        int idx = i0 + i;
        float s = get_mask(masks, mode, g, idx) ? g_scores[idx] : -1e9f;
        mx = fmaxf(mx, s);
    }
    mx = warp_max(mx);
    if ((tid & 31) == 0) sm[tid >> 5] = mx;
    __syncthreads();
    if (tid < 32) {
        float v = (tid < 8) ? sm[tid] : -3.4e38f;
        v = warp_max(v);
        if (tid == 0) sm[0] = v;
    }
    __syncthreads();
    mx = sm[0];
    __syncthreads();

    float sum = 0.f;
    for (int i = tid; i < CHUNK; i += 256) {
        int idx = i0 + i;
        float s = get_mask(masks, mode, g, idx) ? g_scores[idx] : -1e9f;
        sum += __expf(s - mx);
    }
    sum = warp_sum(sum);
    if ((tid & 31) == 0) sm[tid >> 5] = sum;
    __syncthreads();
    if (tid < 32) {
        float v = (tid < 8) ? sm[tid] : 0.f;
        v = warp_sum(v);
        if (tid == 0) {
            g_pm[g * SCH + ch] = mx;
            g_ps[g * SCH + ch] = v;
        }
    }
}

__global__ void softmaxB(const int* __restrict__ cc, float* __restrict__ out) {
    int g = blockIdx.x;
    int lane = threadIdx.x;
    float m = (lane < SCH) ? g_pm[g * SCH + lane] : -3.4e38f;
    float M = warp_max(m);
    float stop = g_stop[g];
    M = fmaxf(M, stop);
    float s = (lane < SCH) ? g_ps[g * SCH + lane] * __expf(m - M) : 0.f;
    float Ssum = warp_sum(s) + __expf(stop - M);
    if (lane == 0) {
        g_smx[g] = M;
        float inv = 1.f / Ssum;
        g_sinv[g] = inv;
        out[(size_t)g * NP1 + NN] = (cc[g] == 0) ? 1.f : __expf(stop - M) * inv;
    }
}

__global__ void __launch_bounds__(256) softmaxC(const void* __restrict__ masks,
                                                const int* __restrict__ cc,
                                                float* __restrict__ out) {
    int g = blockIdx.x >> 3, ch = blockIdx.x & 7;
    int tid = threadIdx.x;
    int i0 = ch * CHUNK;
    int mode = g_maskmode;
    float* o = out + (size_t)g * NP1;
    if (cc[g] == 0) {
        for (int i = tid; i < CHUNK; i += 256) o[i0 + i] = 0.f;
        return;
    }
    float mx = g_smx[g], inv = g_sinv[g];
    for (int i = tid; i < CHUNK; i += 256) {
        int idx = i0 + i;
        float s = get_mask(masks, mode, g, idx) ? g_scores[idx] : -1e9f;
        o[idx] = __expf(s - mx) * inv;
    }
}

// ---------------- host ----------------
extern "C" void kernel_launch(void* const* d_in, const int* in_sizes, int n_in,
                              void* d_out, int out_size) {
    const float* x    = (const float*)d_in[0];
    const int*   ei   = (const int*)d_in[1];
    const int*   cn   = (const int*)d_in[2];
    const int*   cc   = (const int*)d_in[3];
    const void*  masks = d_in[4];
    const float* W1   = (const float*)d_in[5];
    const float* as1w = (const float*)d_in[6];
    const float* ad1w = (const float*)d_in[7];
    const float* b1   = (const float*)d_in[8];
    const float* W2   = (const float*)d_in[9];
    const float* as2w = (const float*)d_in[10];
    const float* ad2w = (const float*)d_in[11];
    const float* b2   = (const float*)d_in[12];
    const float* aw   = (const float*)d_in[13];
    const float* ab   = (const float*)d_in[14];
    const float* sw   = (const float*)d_in[15];
    const float* sb   = (const float*)d_in[16];
    float* out = (float*)d_out;

    unsigned char* h1f8_p;
    __nv_bfloat16* h2bf_p;
    float *h1_p, *as1_p, *ad1_p, *as2_p, *ad2_p;
    cudaGetSymbolAddress((void**)&h1f8_p, g_h1f8);
    cudaGetSymbolAddress((void**)&h1_p, g_h1);
    cudaGetSymbolAddress((void**)&h2bf_p, g_h2bf);
    cudaGetSymbolAddress((void**)&as1_p, g_as1);
    cudaGetSymbolAddress((void**)&ad1_p, g_ad1);
    cudaGetSymbolAddress((void**)&as2_p, g_as2);
    cudaGetSymbolAddress((void**)&ad2_p, g_ad2);

    static cudaStream_t s2 = nullptr;
    static cudaEvent_t evFork = nullptr, evJoin = nullptr, evN2 = nullptr, evCtx = nullptr;
    if (!s2) {
        cudaStreamCreateWithFlags(&s2, cudaStreamNonBlocking);
        cudaEventCreateWithFlags(&evFork, cudaEventDisableTiming);
        cudaEventCreateWithFlags(&evJoin, cudaEventDisableTiming);
        cudaEventCreateWithFlags(&evN2, cudaEventDisableTiming);
        cudaEventCreateWithFlags(&evCtx, cudaEventDisableTiming);
    }

    // fork: detect + CSR build on s2; GEMM1 (independent) on main
    cudaEventRecord(evFork, 0);
    cudaStreamWaitEvent(s2, evFork, 0);
    detect_all<<<1, 32, 0, s2>>>((const unsigned*)ei, (const unsigned*)masks);
    zero_cnt<<<(NN + 255) / 256, 256, 0, s2>>>();
    hist_kernel<<<(EE + 255) / 256, 256, 0, s2>>>(ei);
    scan1<<<NB_SCAN, 256, 0, s2>>>();
    scan2<<<1, 256, 0, s2>>>();
    scan3<<<NB_SCAN, 256, 0, s2>>>();
    fill_kernel<<<(EE + 255) / 256, 256, 0, s2>>>(ei);
    cudaEventRecord(evJoin, s2);

    // layer 1 GEMM (+att dots + fp8 store fused)
    gemm_att<1><<<dim3(HEADS, (NN + 127) / 128), 256>>>(x, W1, h1f8_p, as1w, ad1w,
                                                        as1_p, ad1_p, HEADS, NN, HC, FIN);
    cudaStreamWaitEvent(0, evJoin, 0);
    node1_kernel<<<(NN + 7) / 8, 256>>>(b1);

    // layer 2
    gemm_att<0><<<dim3(1, (NN + 127) / 128), 256>>>(h1_p, W2, h2bf_p, as2w, ad2w,
                                                    as2_p, ad2_p, 1, NN, HID, HC);
    node2_kernel<<<(NN + 7) / 8, 256>>>(b2, aw, ab);

    // heads: context on s2 overlaps softmaxA on main
    cudaEventRecord(evN2, 0);
    cudaStreamWaitEvent(s2, evN2, 0);
    context_kernel<<<NG, 64, 0, s2>>>(cn, cc, sw, sb);
    cudaEventRecord(evCtx, s2);
    softmaxA<<<NG * SCH, 256>>>(masks);
    cudaStreamWaitEvent(0, evCtx, 0);
    softmaxB<<<NG, 32>>>(cc, out);
    softmaxC<<<NG * SCH, 256>>>(masks, cc, out);
}

// round 12
// speedup vs baseline: 7.5676x; 1.0503x over previous
#include <cuda_runtime.h>
#include <cuda_bf16.h>
#include <cuda_fp16.h>

#define NN 50000
#define NE 800000
#define EE (NE + NN)
#define NG 32
#define KMAX 16
#define FIN 128
#define HID 64
#define HEADS 4
#define HC 256          // HEADS*HID
#define NP1 (NN + 1)
#define CAP 160
#define NB_SCAN ((NN + 255) / 256)
#define SCH 8
#define CHUNK (NN / SCH)   // 6250

// ---------------- scratch ----------------
__device__ unsigned char g_h1f8[NN * HC];    // x@W1 in fp8 e4m3 (gather operand)
__device__ float         g_h1  [NN * HC];    // after GAT1 + relu (GEMM2 input)
__device__ __nv_bfloat16 g_h2bf[NN * HID];   // h1@W2 in bf16 (gather operand)
__device__ float         g_h2  [NN * HID];   // after GAT2 (+b2)
__device__ float         g_as1 [NN * HEADS];
__device__ float         g_ad1 [NN * HEADS];
__device__ float         g_as2 [NN];
__device__ float         g_ad2 [NN];
__device__ float         g_scores[NN];
__device__ float         g_stop  [NG];
__device__ int           g_ei64;
__device__ int           g_maskmode;         // 0=uint8, 1=int32, 2=float32

// CSR scratch
__device__ int g_cnt [NN];
__device__ int g_off [NN];
__device__ int g_woff[NN];
__device__ int g_csrc[EE];
__device__ int g_bsum[NB_SCAN];
__device__ int g_bsumoff[NB_SCAN];

// softmax partials
__device__ float g_pm[NG * SCH];
__device__ float g_ps[NG * SCH];
__device__ float g_smx[NG];
__device__ float g_sinv[NG];

// ---------------- helpers ----------------
__device__ __forceinline__ float lrelu(float a) { return a > 0.f ? a : 0.2f * a; }

__device__ __forceinline__ float warp_sum(float v) {
#pragma unroll
    for (int o = 16; o; o >>= 1) v += __shfl_xor_sync(0xffffffffu, v, o);
    return v;
}
__device__ __forceinline__ float warp_max(float v) {
#pragma unroll
    for (int o = 16; o; o >>= 1) v = fmaxf(v, __shfl_xor_sync(0xffffffffu, v, o));
    return v;
}

__device__ __forceinline__ unsigned f2tf(float f) {
    unsigned u;
    asm("cvt.rna.tf32.f32 %0, %1;" : "=r"(u) : "f"(f));
    return u;
}
__device__ __forceinline__ void mma_tf32(float* c, const unsigned* a, const unsigned* b) {
    asm volatile(
        "mma.sync.aligned.m16n8k8.row.col.f32.tf32.tf32.f32 "
        "{%0,%1,%2,%3},{%4,%5,%6,%7},{%8,%9},{%0,%1,%2,%3};"
        : "+f"(c[0]), "+f"(c[1]), "+f"(c[2]), "+f"(c[3])
        : "r"(a[0]), "r"(a[1]), "r"(a[2]), "r"(a[3]), "r"(b[0]), "r"(b[1]));
}

// fp8 e4m3 pack: returns (fp8(hi)<<8)|fp8(lo) -> little-endian bytes [lo, hi]
__device__ __forceinline__ unsigned short f2_to_fp8x2(float hi, float lo) {
    unsigned short r;
    asm("cvt.rn.satfinite.e4m3x2.f32 %0, %1, %2;" : "=h"(r) : "f"(hi), "f"(lo));
    return r;
}
// fp8x2 (low 16 bits) -> half2, low fp8 -> .x
__device__ __forceinline__ __half2 fp8x2_to_h2(unsigned v) {
    unsigned r;
    unsigned short s = (unsigned short)v;
    asm("cvt.rn.f16x2.e4m3x2 %0, %1;" : "=r"(r) : "h"(s));
    return *(__half2*)&r;
}

__device__ __forceinline__ void load_edge(const int* __restrict__ ei, int e, int& s, int& d) {
    if (e >= NE) { s = d = e - NE; return; }
    if (g_ei64) { s = ei[2 * e]; d = ei[2 * (NE + e)]; }
    else        { s = ei[e];     d = ei[NE + e]; }
}

__global__ void detect_all(const unsigned* __restrict__ ei, const unsigned* __restrict__ m) {
    int lane = threadIdx.x;
    int f32 = 0, multi = 0;
    for (int i = lane; i < 2048; i += 32) {
        unsigned w = m[i];
        if (w == 0x3F800000u) f32 = 1;
        else if (w > 1u) multi = 1;
    }
    f32 = __any_sync(0xffffffffu, f32);
    multi = __any_sync(0xffffffffu, multi);
    if (lane == 0) {
        g_maskmode = f32 ? 2 : (multi ? 0 : 1);
        unsigned o = ei[1] | ei[3] | ei[5] | ei[7] | ei[9] | ei[11] | ei[13] | ei[15];
        g_ei64 = (o == 0u) ? 1 : 0;
    }
}

// ---------------- CSR construction ----------------
__global__ void zero_cnt() {
    int i = blockIdx.x * blockDim.x + threadIdx.x;
    if (i < NN) g_cnt[i] = 0;
}
__global__ void hist_kernel(const int* __restrict__ ei) {
    int e = blockIdx.x * blockDim.x + threadIdx.x;
    if (e >= EE) return;
    int s, d;
    load_edge(ei, e, s, d);
    atomicAdd(&g_cnt[d], 1);
}
__global__ void scan1() {
    __shared__ int sh[256];
    int t = threadIdx.x;
    int i = blockIdx.x * 256 + t;
    int v = (i < NN) ? g_cnt[i] : 0;
    sh[t] = v;
    __syncthreads();
#pragma unroll
    for (int off = 1; off < 256; off <<= 1) {
        int add = (t >= off) ? sh[t - off] : 0;
        __syncthreads();
        sh[t] += add;
        __syncthreads();
    }
    if (i < NN) g_off[i] = sh[t] - v;
    if (t == 255) g_bsum[blockIdx.x] = sh[255];
}
__global__ void scan2() {
    __shared__ int sh[256];
    int t = threadIdx.x;
    int v = (t < NB_SCAN) ? g_bsum[t] : 0;
    sh[t] = v;
    __syncthreads();
#pragma unroll
    for (int off = 1; off < 256; off <<= 1) {
        int add = (t >= off) ? sh[t - off] : 0;
        __syncthreads();
        sh[t] += add;
        __syncthreads();
    }
    if (t < NB_SCAN) g_bsumoff[t] = sh[t] - v;
}
__global__ void scan3() {
    int i = blockIdx.x * blockDim.x + threadIdx.x;
    if (i >= NN) return;
    int o = g_off[i] + g_bsumoff[i >> 8];
    g_off[i] = o;
    g_woff[i] = o;
}
__global__ void fill_kernel(const int* __restrict__ ei) {
    int e = blockIdx.x * blockDim.x + threadIdx.x;
    if (e >= EE) return;
    int s, d;
    load_edge(ei, e, s, d);
    int pos = atomicAdd(&g_woff[d], 1);
    g_csrc[pos] = s;
}

// ---------------- TF32 GEMM + fused attention-dot epilogue + fp8/bf16 store ----------------
template <int STORE_FP8>
__global__ void __launch_bounds__(256) gemm_att(const float* __restrict__ A,
                                                const float* __restrict__ B,
                                                void* __restrict__ Cout,
                                                const float* __restrict__ att_s,
                                                const float* __restrict__ att_d,
                                                float* __restrict__ as_out,
                                                float* __restrict__ ad_out,
                                                int S, int M, int N, int K) {
    const int BM = 128, BK = 16;
    __shared__ float As[BK][BM + 4];
    __shared__ float Bs[BK][64 + 4];
    __shared__ float sAttS[64], sAttD[64];
    __shared__ float sRedS[2][128], sRedD[2][128];
    int tid = threadIdx.x;
    int bx = blockIdx.x;
    int bm = blockIdx.y * BM, bn = bx * 64;
    int wid = tid >> 5, lane = tid & 31;
    int wm = wid & 3, wn = wid >> 2;
    int g = lane >> 2, t = lane & 3;

    if (tid < 64) sAttS[tid] = att_s[bx * 64 + tid];
    else if (tid < 128) sAttD[tid - 64] = att_d[bx * 64 + tid - 64];

    float acc[2][4][4];
#pragma unroll
    for (int mf = 0; mf < 2; mf++)
#pragma unroll
        for (int nf = 0; nf < 4; nf++)
#pragma unroll
            for (int i = 0; i < 4; i++) acc[mf][nf][i] = 0.f;

    for (int k0 = 0; k0 < K; k0 += BK) {
#pragma unroll
        for (int i = 0; i < 2; i++) {
            int row = (tid >> 2) + i * 64;
            int c4 = (tid & 3) * 4;
            float4 v = make_float4(0.f, 0.f, 0.f, 0.f);
            if (bm + row < M)
                v = *(const float4*)&A[(size_t)(bm + row) * K + k0 + c4];
            As[c4 + 0][row] = v.x;
            As[c4 + 1][row] = v.y;
            As[c4 + 2][row] = v.z;
            As[c4 + 3][row] = v.w;
        }
        {
            int bRow = tid >> 4, bCol = (tid & 15) * 4;
            *(float4*)&Bs[bRow][bCol] = *(const float4*)&B[(size_t)(k0 + bRow) * N + bn + bCol];
        }
        __syncthreads();
#pragma unroll
        for (int k2 = 0; k2 < 2; k2++) {
            int kk = k2 * 8;
            unsigned aF[2][4], bF[4][2];
#pragma unroll
            for (int mf = 0; mf < 2; mf++) {
                int m0 = wm * 32 + mf * 16 + g;
                aF[mf][0] = f2tf(As[kk + t][m0]);
                aF[mf][1] = f2tf(As[kk + t][m0 + 8]);
                aF[mf][2] = f2tf(As[kk + t + 4][m0]);
                aF[mf][3] = f2tf(As[kk + t + 4][m0 + 8]);
            }
#pragma unroll
            for (int nf = 0; nf < 4; nf++) {
                int n0 = wn * 32 + nf * 8 + g;
                bF[nf][0] = f2tf(Bs[kk + t][n0]);
                bF[nf][1] = f2tf(Bs[kk + t + 4][n0]);
            }
#pragma unroll
            for (int mf = 0; mf < 2; mf++)
#pragma unroll
                for (int nf = 0; nf < 4; nf++)
                    mma_tf32(acc[mf][nf], aF[mf], bF[nf]);
        }
        __syncthreads();
    }

    // epilogue: quantized store + per-row attention dots
    float psS[2][2] = {{0.f, 0.f}, {0.f, 0.f}};
    float psD[2][2] = {{0.f, 0.f}, {0.f, 0.f}};
#pragma unroll
    for (int mf = 0; mf < 2; mf++) {
#pragma unroll
        for (int nf = 0; nf < 4; nf++) {
            int colL = wn * 32 + nf * 8 + 2 * t;
            float aS0 = sAttS[colL], aS1 = sAttS[colL + 1];
            float aD0 = sAttD[colL], aD1 = sAttD[colL + 1];
            float* c = acc[mf][nf];
            psS[mf][0] += c[0] * aS0 + c[1] * aS1;
            psS[mf][1] += c[2] * aS0 + c[3] * aS1;
            psD[mf][0] += c[0] * aD0 + c[1] * aD1;
            psD[mf][1] += c[2] * aD0 + c[3] * aD1;
            int r = bm + wm * 32 + mf * 16 + g;
            if (STORE_FP8) {
                unsigned char* Cf8 = (unsigned char*)Cout;
                unsigned short p0 = f2_to_fp8x2(c[1], c[0]);
                unsigned short p1 = f2_to_fp8x2(c[3], c[2]);
                if (r < M)     *(unsigned short*)&Cf8[(size_t)r * N + bn + colL] = p0;
                if (r + 8 < M) *(unsigned short*)&Cf8[(size_t)(r + 8) * N + bn + colL] = p1;
            } else {
                __nv_bfloat16* Cbf = (__nv_bfloat16*)Cout;
                __nv_bfloat162 p0 = __floats2bfloat162_rn(c[0], c[1]);
                __nv_bfloat162 p1 = __floats2bfloat162_rn(c[2], c[3]);
                if (r < M)     *(__nv_bfloat162*)&Cbf[(size_t)r * N + bn + colL] = p0;
                if (r + 8 < M) *(__nv_bfloat162*)&Cbf[(size_t)(r + 8) * N + bn + colL] = p1;
            }
        }
    }
#pragma unroll
    for (int mf = 0; mf < 2; mf++)
#pragma unroll
        for (int ro = 0; ro < 2; ro++) {
            psS[mf][ro] += __shfl_xor_sync(0xffffffffu, psS[mf][ro], 1);
            psS[mf][ro] += __shfl_xor_sync(0xffffffffu, psS[mf][ro], 2);
            psD[mf][ro] += __shfl_xor_sync(0xffffffffu, psD[mf][ro], 1);
            psD[mf][ro] += __shfl_xor_sync(0xffffffffu, psD[mf][ro], 2);
        }
    if (t == 0) {
#pragma unroll
        for (int mf = 0; mf < 2; mf++)
#pragma unroll
            for (int ro = 0; ro < 2; ro++) {
                int rl = wm * 32 + mf * 16 + ro * 8 + g;
                sRedS[wn][rl] = psS[mf][ro];
                sRedD[wn][rl] = psD[mf][ro];
            }
    }
    __syncthreads();
    if (tid < 128 && bm + tid < M) {
        as_out[(size_t)(bm + tid) * S + bx] = sRedS[0][tid] + sRedS[1][tid];
        ad_out[(size_t)(bm + tid) * S + bx] = sRedD[0][tid] + sRedD[1][tid];
    }
}

// ---------------- layer 1 gather: warp per dst node (no-max softmax, fp8 rows, 4-wide pipeline) ----------------
__global__ void __launch_bounds__(256) node1_kernel(const float* __restrict__ b1) {
    __shared__ float s_ex[8][CAP * 4];
    __shared__ int   s_src[8][CAP];
    int w = (blockIdx.x * blockDim.x + threadIdx.x) >> 5;
    int lane = threadIdx.x & 31;
    int wl = threadIdx.x >> 5;
    if (w >= NN) return;
    int base = g_off[w];
    int deg  = g_cnt[w];
    float4 ad = *(const float4*)(g_ad1 + (size_t)w * 4);

    // pass A: ex = exp(lrelu(as+ad)) per head; cache; accumulate denominator
    float4 den = make_float4(0.f, 0.f, 0.f, 0.f);
    for (int j = lane; j < deg; j += 32) {
        int s = g_csrc[base + j];
        float4 as = *(const float4*)(g_as1 + (size_t)s * 4);
        float4 ex;
        ex.x = __expf(lrelu(as.x + ad.x));
        ex.y = __expf(lrelu(as.y + ad.y));
        ex.z = __expf(lrelu(as.z + ad.z));
        ex.w = __expf(lrelu(as.w + ad.w));
        if (j < CAP) {
            s_src[wl][j] = s;
            *(float4*)&s_ex[wl][j * 4] = ex;
        }
        den.x += ex.x; den.y += ex.y; den.z += ex.z; den.w += ex.w;
    }
    den.x = warp_sum(den.x); den.y = warp_sum(den.y);
    den.z = warp_sum(den.z); den.w = warp_sum(den.w);
    __syncwarp();

    // pass B: feature accumulation in f16x2, explicit 4-wide load pipeline
    int head = lane >> 3;
    float adh = head == 0 ? ad.x : head == 1 ? ad.y : head == 2 ? ad.z : ad.w;
    float dh  = head == 0 ? den.x : head == 1 ? den.y : head == 2 ? den.z : den.w;
    __half2 hz = __float2half2_rn(0.f);
    __half2 hacc0 = hz, hacc1 = hz, hacc2 = hz, hacc3 = hz;

    if (deg <= CAP) {
        int j = 0;
        for (; j + 4 <= deg; j += 4) {
            // batch: independent index + coeff + row loads (MLP=4)
            int s0 = s_src[wl][j + 0];
            int s1 = s_src[wl][j + 1];
            int s2 = s_src[wl][j + 2];
            int s3 = s_src[wl][j + 3];
            float e0 = s_ex[wl][(j + 0) * 4 + head];
            float e1 = s_ex[wl][(j + 1) * 4 + head];
            float e2 = s_ex[wl][(j + 2) * 4 + head];
            float e3 = s_ex[wl][(j + 3) * 4 + head];
            uint2 r0 = *(const uint2*)(g_h1f8 + (size_t)s0 * HC + lane * 8);
            uint2 r1 = *(const uint2*)(g_h1f8 + (size_t)s1 * HC + lane * 8);
            uint2 r2 = *(const uint2*)(g_h1f8 + (size_t)s2 * HC + lane * 8);
            uint2 r3 = *(const uint2*)(g_h1f8 + (size_t)s3 * HC + lane * 8);
            __half2 x0 = __float2half2_rn(e0);
            __half2 x1 = __float2half2_rn(e1);
            __half2 x2 = __float2half2_rn(e2);
            __half2 x3 = __float2half2_rn(e3);
            hacc0 = __hfma2(x0, fp8x2_to_h2(r0.x), hacc0);
            hacc1 = __hfma2(x0, fp8x2_to_h2(r0.x >> 16), hacc1);
            hacc2 = __hfma2(x0, fp8x2_to_h2(r0.y), hacc2);
            hacc3 = __hfma2(x0, fp8x2_to_h2(r0.y >> 16), hacc3);
            hacc0 = __hfma2(x1, fp8x2_to_h2(r1.x), hacc0);
            hacc1 = __hfma2(x1, fp8x2_to_h2(r1.x >> 16), hacc1);
            hacc2 = __hfma2(x1, fp8x2_to_h2(r1.y), hacc2);
            hacc3 = __hfma2(x1, fp8x2_to_h2(r1.y >> 16), hacc3);
            hacc0 = __hfma2(x2, fp8x2_to_h2(r2.x), hacc0);
            hacc1 = __hfma2(x2, fp8x2_to_h2(r2.x >> 16), hacc1);
            hacc2 = __hfma2(x2, fp8x2_to_h2(r2.y), hacc2);
            hacc3 = __hfma2(x2, fp8x2_to_h2(r2.y >> 16), hacc3);
            hacc0 = __hfma2(x3, fp8x2_to_h2(r3.x), hacc0);
            hacc1 = __hfma2(x3, fp8x2_to_h2(r3.x >> 16), hacc1);
            hacc2 = __hfma2(x3, fp8x2_to_h2(r3.y), hacc2);
            hacc3 = __hfma2(x3, fp8x2_to_h2(r3.y >> 16), hacc3);
        }
        for (; j < deg; j++) {
            int s = s_src[wl][j];
            float ex = s_ex[wl][j * 4 + head];
            uint2 r = *(const uint2*)(g_h1f8 + (size_t)s * HC + lane * 8);
            __half2 exh = __float2half2_rn(ex);
            hacc0 = __hfma2(exh, fp8x2_to_h2(r.x), hacc0);
            hacc1 = __hfma2(exh, fp8x2_to_h2(r.x >> 16), hacc1);
            hacc2 = __hfma2(exh, fp8x2_to_h2(r.y), hacc2);
            hacc3 = __hfma2(exh, fp8x2_to_h2(r.y >> 16), hacc3);
        }
    } else {
        for (int j = 0; j < deg; j++) {
            int s; float ex;
            if (j < CAP) {
                s = s_src[wl][j];
                ex = s_ex[wl][j * 4 + head];
            } else {
                s = g_csrc[base + j];
                ex = __expf(lrelu(g_as1[(size_t)s * 4 + head] + adh));
            }
            uint2 r = *(const uint2*)(g_h1f8 + (size_t)s * HC + lane * 8);
            __half2 exh = __float2half2_rn(ex);
            hacc0 = __hfma2(exh, fp8x2_to_h2(r.x), hacc0);
            hacc1 = __hfma2(exh, fp8x2_to_h2(r.x >> 16), hacc1);
            hacc2 = __hfma2(exh, fp8x2_to_h2(r.y), hacc2);
            hacc3 = __hfma2(exh, fp8x2_to_h2(r.y >> 16), hacc3);
        }
    }
    float inv = 1.f / dh;
    float2 a0 = __half22float2(hacc0);
    float2 a1 = __half22float2(hacc1);
    float2 a2 = __half22float2(hacc2);
    float2 a3 = __half22float2(hacc3);
    int f = lane * 8;
    const float4* bp = (const float4*)(b1 + f);
    float4 bb0 = bp[0], bb1 = bp[1];
    float4 o0, o1;
    o0.x = fmaxf(a0.x * inv + bb0.x, 0.f);
    o0.y = fmaxf(a0.y * inv + bb0.y, 0.f);
    o0.z = fmaxf(a1.x * inv + bb0.z, 0.f);
    o0.w = fmaxf(a1.y * inv + bb0.w, 0.f);
    o1.x = fmaxf(a2.x * inv + bb1.x, 0.f);
    o1.y = fmaxf(a2.y * inv + bb1.y, 0.f);
    o1.z = fmaxf(a3.x * inv + bb1.z, 0.f);
    o1.w = fmaxf(a3.y * inv + bb1.w, 0.f);
    float4* op = (float4*)(g_h1 + (size_t)w * HC + f);
    op[0] = o0;
    op[1] = o1;
}

// ---------------- layer 2 gather + node scores (no-max softmax, 4-wide pipeline) ----------------
__global__ void __launch_bounds__(256) node2_kernel(const float* __restrict__ b2,
                                                    const float* __restrict__ aw,
                                                    const float* __restrict__ ab) {
    __shared__ float s_ex[8][CAP];
    __shared__ int   s_src[8][CAP];
    int w = (blockIdx.x * blockDim.x + threadIdx.x) >> 5;
    int lane = threadIdx.x & 31;
    int wl = threadIdx.x >> 5;
    if (w >= NN) return;
    int base = g_off[w];
    int deg  = g_cnt[w];
    float ad = g_ad2[w];

    float den = 0.f;
    for (int j = lane; j < deg; j += 32) {
        int s = g_csrc[base + j];
        float ex = __expf(lrelu(g_as2[s] + ad));
        if (j < CAP) { s_src[wl][j] = s; s_ex[wl][j] = ex; }
        den += ex;
    }
    den = warp_sum(den);
    __syncwarp();

    float acc0 = 0.f, acc1 = 0.f;
    if (deg <= CAP) {
        int j = 0;
        for (; j + 4 <= deg; j += 4) {
            int s0 = s_src[wl][j + 0];
            int s1 = s_src[wl][j + 1];
            int s2 = s_src[wl][j + 2];
            int s3 = s_src[wl][j + 3];
            float e0 = s_ex[wl][j + 0];
            float e1 = s_ex[wl][j + 1];
            float e2 = s_ex[wl][j + 2];
            float e3 = s_ex[wl][j + 3];
            __nv_bfloat162 v0 = *(const __nv_bfloat162*)(g_h2bf + (size_t)s0 * HID + lane * 2);
            __nv_bfloat162 v1 = *(const __nv_bfloat162*)(g_h2bf + (size_t)s1 * HID + lane * 2);
            __nv_bfloat162 v2 = *(const __nv_bfloat162*)(g_h2bf + (size_t)s2 * HID + lane * 2);
            __nv_bfloat162 v3 = *(const __nv_bfloat162*)(g_h2bf + (size_t)s3 * HID + lane * 2);
            float2 f0 = __bfloat1622float2(v0);
            float2 f1 = __bfloat1622float2(v1);
            float2 f2 = __bfloat1622float2(v2);
            float2 f3 = __bfloat1622float2(v3);
            acc0 += e0 * f0.x + e1 * f1.x + e2 * f2.x + e3 * f3.x;
            acc1 += e0 * f0.y + e1 * f1.y + e2 * f2.y + e3 * f3.y;
        }
        for (; j < deg; j++) {
            int s = s_src[wl][j];
            float ex = s_ex[wl][j];
            __nv_bfloat162 vb = *(const __nv_bfloat162*)(g_h2bf + (size_t)s * HID + lane * 2);
            float2 v = __bfloat1622float2(vb);
            acc0 += ex * v.x;
            acc1 += ex * v.y;
        }
    } else {
        for (int j = 0; j < deg; j++) {
            int s; float ex;
            if (j < CAP) { s = s_src[wl][j]; ex = s_ex[wl][j]; }
            else {
                s = g_csrc[base + j];
                ex = __expf(lrelu(g_as2[s] + ad));
            }
            __nv_bfloat162 vb = *(const __nv_bfloat162*)(g_h2bf + (size_t)s * HID + lane * 2);
            float2 v = __bfloat1622float2(vb);
            acc0 += ex * v.x;
            acc1 += ex * v.y;
        }
    }
    float inv = 1.f / den;
    int c = lane * 2;
    float h0 = acc0 * inv + b2[c];
    float h1 = acc1 * inv + b2[c + 1];
    *(float2*)(g_h2 + (size_t)w * HID + c) = make_float2(h0, h1);
    float sc = warp_sum(h0 * aw[c] + h1 * aw[c + 1]);
    if (lane == 0) g_scores[w] = tanhf(sc + ab[0]);
}

// ---------------- per-graph pooled stop score ----------------
__global__ void context_kernel(const int* __restrict__ cn, const int* __restrict__ cc,
                               const float* __restrict__ sw, const float* __restrict__ sb) {
    int g = blockIdx.x;
    int c = threadIdx.x;   // 64 threads
    int cnt = cc[g];
    float sum = 0.f;
#pragma unroll
    for (int k = 0; k < KMAX; k++) {
        if (k < cnt) {
            int n = cn[g * KMAX + k];
            sum += g_h2[(size_t)n * HID + c];
        }
    }
    int cm = cnt > 1 ? cnt : 1;
    float ctx = sum / (float)cm;
    __shared__ float red[64];
    red[c] = ctx * sw[c];
    __syncthreads();
    for (int o = 32; o; o >>= 1) {
        if (c < o) red[c] += red[c + o];
        __syncthreads();
    }
    if (c == 0) g_stop[g] = tanhf(red[0] + sb[0]);
}

__device__ __forceinline__ bool get_mask(const void* masks, int mode, int g, int i) {
    if (mode == 2) return ((const float*)masks)[(size_t)g * NN + i] != 0.f;
    if (mode == 1) return ((const int*)masks)[(size_t)g * NN + i] != 0;
    return ((const unsigned char*)masks)[(size_t)g * NN + i] != 0;
}

// ---------------- split softmax ----------------
__global__ void __launch_bounds__(256) softmaxA(const void* __restrict__ masks) {
    int g = blockIdx.x >> 3, ch = blockIdx.x & 7;
    int tid = threadIdx.x;
    int i0 = ch * CHUNK;
    int mode = g_maskmode;
    __shared__ float sm[8];

    float mx = -3.4e38f;
    for (int i = tid; i < CHUNK; i += 256) {
        int idx = i0 + i;
        float s = get_mask(masks, mode, g, idx) ? g_scores[idx] : -1e9f;
        mx = fmaxf(mx, s);
    }
    mx = warp_max(mx);
    if ((tid & 31) == 0) sm[tid >> 5] = mx;
    __syncthreads();
    if (tid < 32) {
        float v = (tid < 8) ? sm[tid] : -3.4e38f;
        v = warp_max(v);
        if (tid == 0) sm[0] = v;
    }
    __syncthreads();
    mx = sm[0];
    __syncthreads();

    float sum = 0.f;
    for (int i = tid; i < CHUNK; i += 256) {
        int idx = i0 + i;
        float s = get_mask(masks, mode, g, idx) ? g_scores[idx] : -1e9f;
        sum += __expf(s - mx);
    }
    sum = warp_sum(sum);
    if ((tid & 31) == 0) sm[tid >> 5] = sum;
    __syncthreads();
    if (tid < 32) {
        float v = (tid < 8) ? sm[tid] : 0.f;
        v = warp_sum(v);
        if (tid == 0) {
            g_pm[g * SCH + ch] = mx;
            g_ps[g * SCH + ch] = v;
        }
    }
}

__global__ void softmaxB(const int* __restrict__ cc, float* __restrict__ out) {
    int g = blockIdx.x;
    int lane = threadIdx.x;
    float m = (lane < SCH) ? g_pm[g * SCH + lane] : -3.4e38f;
    float M = warp_max(m);
    float stop = g_stop[g];
    M = fmaxf(M, stop);
    float s = (lane < SCH) ? g_ps[g * SCH + lane] * __expf(m - M) : 0.f;
    float Ssum = warp_sum(s) + __expf(stop - M);
    if (lane == 0) {
        g_smx[g] = M;
        float inv = 1.f / Ssum;
        g_sinv[g] = inv;
        out[(size_t)g * NP1 + NN] = (cc[g] == 0) ? 1.f : __expf(stop - M) * inv;
    }
}

__global__ void __launch_bounds__(256) softmaxC(const void* __restrict__ masks,
                                                const int* __restrict__ cc,
                                                float* __restrict__ out) {
    int g = blockIdx.x >> 3, ch = blockIdx.x & 7;
    int tid = threadIdx.x;
    int i0 = ch * CHUNK;
    int mode = g_maskmode;
    float* o = out + (size_t)g * NP1;
    if (cc[g] == 0) {
        for (int i = tid; i < CHUNK; i += 256) o[i0 + i] = 0.f;
        return;
    }
    float mx = g_smx[g], inv = g_sinv[g];
    for (int i = tid; i < CHUNK; i += 256) {
        int idx = i0 + i;
        float s = get_mask(masks, mode, g, idx) ? g_scores[idx] : -1e9f;
        o[idx] = __expf(s - mx) * inv;
    }
}

// ---------------- host ----------------
extern "C" void kernel_launch(void* const* d_in, const int* in_sizes, int n_in,
                              void* d_out, int out_size) {
    const float* x    = (const float*)d_in[0];
    const int*   ei   = (const int*)d_in[1];
    const int*   cn   = (const int*)d_in[2];
    const int*   cc   = (const int*)d_in[3];
    const void*  masks = d_in[4];
    const float* W1   = (const float*)d_in[5];
    const float* as1w = (const float*)d_in[6];
    const float* ad1w = (const float*)d_in[7];
    const float* b1   = (const float*)d_in[8];
    const float* W2   = (const float*)d_in[9];
    const float* as2w = (const float*)d_in[10];
    const float* ad2w = (const float*)d_in[11];
    const float* b2   = (const float*)d_in[12];
    const float* aw   = (const float*)d_in[13];
    const float* ab   = (const float*)d_in[14];
    const float* sw   = (const float*)d_in[15];
    const float* sb   = (const float*)d_in[16];
    float* out = (float*)d_out;

    unsigned char* h1f8_p;
    __nv_bfloat16* h2bf_p;
    float *h1_p, *as1_p, *ad1_p, *as2_p, *ad2_p;
    cudaGetSymbolAddress((void**)&h1f8_p, g_h1f8);
    cudaGetSymbolAddress((void**)&h1_p, g_h1);
    cudaGetSymbolAddress((void**)&h2bf_p, g_h2bf);
    cudaGetSymbolAddress((void**)&as1_p, g_as1);
    cudaGetSymbolAddress((void**)&ad1_p, g_ad1);
    cudaGetSymbolAddress((void**)&as2_p, g_as2);
    cudaGetSymbolAddress((void**)&ad2_p, g_ad2);

    static cudaStream_t s2 = nullptr;
    static cudaEvent_t evFork = nullptr, evJoin = nullptr, evN2 = nullptr, evCtx = nullptr;
    if (!s2) {
        cudaStreamCreateWithFlags(&s2, cudaStreamNonBlocking);
        cudaEventCreateWithFlags(&evFork, cudaEventDisableTiming);
        cudaEventCreateWithFlags(&evJoin, cudaEventDisableTiming);
        cudaEventCreateWithFlags(&evN2, cudaEventDisableTiming);
        cudaEventCreateWithFlags(&evCtx, cudaEventDisableTiming);
    }

    // fork: detect + CSR build on s2; GEMM1 (independent) on main
    cudaEventRecord(evFork, 0);
    cudaStreamWaitEvent(s2, evFork, 0);
    detect_all<<<1, 32, 0, s2>>>((const unsigned*)ei, (const unsigned*)masks);
    zero_cnt<<<(NN + 255) / 256, 256, 0, s2>>>();
    hist_kernel<<<(EE + 255) / 256, 256, 0, s2>>>(ei);
    scan1<<<NB_SCAN, 256, 0, s2>>>();
    scan2<<<1, 256, 0, s2>>>();
    scan3<<<NB_SCAN, 256, 0, s2>>>();
    fill_kernel<<<(EE + 255) / 256, 256, 0, s2>>>(ei);
    cudaEventRecord(evJoin, s2);

    // layer 1 GEMM (+att dots + fp8 store fused)
    gemm_att<1><<<dim3(HEADS, (NN + 127) / 128), 256>>>(x, W1, h1f8_p, as1w, ad1w,
                                                        as1_p, ad1_p, HEADS, NN, HC, FIN);
    cudaStreamWaitEvent(0, evJoin, 0);
    node1_kernel<<<(NN + 7) / 8, 256>>>(b1);

    // layer 2
    gemm_att<0><<<dim3(1, (NN + 127) / 128), 256>>>(h1_p, W2, h2bf_p, as2w, ad2w,
                                                    as2_p, ad2_p, 1, NN, HID, HC);
    node2_kernel<<<(NN + 7) / 8, 256>>>(b2, aw, ab);

    // heads: context on s2 overlaps softmaxA on main
    cudaEventRecord(evN2, 0);
    cudaStreamWaitEvent(s2, evN2, 0);
    context_kernel<<<NG, 64, 0, s2>>>(cn, cc, sw, sb);
    cudaEventRecord(evCtx, s2);
    softmaxA<<<NG * SCH, 256>>>(masks);
    cudaStreamWaitEvent(0, evCtx, 0);
    softmaxB<<<NG, 32>>>(cc, out);
    softmaxC<<<NG * SCH, 256>>>(masks, cc, out);
}

// round 15
// speedup vs baseline: 7.5952x; 1.0037x over previous
#include <cuda_runtime.h>
#include <cuda_bf16.h>
#include <cuda_fp16.h>

#define NN 50000
#define NE 800000
#define EE (NE + NN)
#define NG 32
#define KMAX 16
#define FIN 128
#define HID 64
#define HEADS 4
#define HC 256          // HEADS*HID
#define NP1 (NN + 1)
#define CAP 160
#define NB_SCAN ((NN + 255) / 256)
#define SCH 8
#define CHUNK (NN / SCH)   // 6250

// ---------------- scratch ----------------
__device__ unsigned char g_h1f8[NN * HC];    // x@W1 in fp8 e4m3 (gather operand)
__device__ float         g_h1  [NN * HC];    // after GAT1 + relu (GEMM2 input)
__device__ __nv_bfloat16 g_h2bf[NN * HID];   // h1@W2 in bf16 (gather operand)
__device__ float         g_h2  [NN * HID];   // after GAT2 (+b2)
__device__ float         g_as1 [NN * HEADS];
__device__ float         g_ad1 [NN * HEADS];
__device__ float         g_as2 [NN];
__device__ float         g_ad2 [NN];
__device__ float         g_scores[NN];
__device__ float         g_stop  [NG];
__device__ int           g_ei64;
__device__ int           g_maskmode;         // 0=uint8, 1=int32, 2=float32

// CSR scratch
__device__ int g_cnt [NN];
__device__ int g_off [NN];
__device__ int g_woff[NN];
__device__ int g_csrc[EE];
__device__ int g_bsum[NB_SCAN];
__device__ int g_bsumoff[NB_SCAN];

// softmax partials
__device__ float g_pm[NG * SCH];
__device__ float g_ps[NG * SCH];
__device__ float g_smx[NG];
__device__ float g_sinv[NG];

// ---------------- helpers ----------------
__device__ __forceinline__ float lrelu(float a) { return a > 0.f ? a : 0.2f * a; }

__device__ __forceinline__ float warp_sum(float v) {
#pragma unroll
    for (int o = 16; o; o >>= 1) v += __shfl_xor_sync(0xffffffffu, v, o);
    return v;
}
__device__ __forceinline__ float warp_max(float v) {
#pragma unroll
    for (int o = 16; o; o >>= 1) v = fmaxf(v, __shfl_xor_sync(0xffffffffu, v, o));
    return v;
}

__device__ __forceinline__ unsigned f2tf(float f) {
    unsigned u;
    asm("cvt.rna.tf32.f32 %0, %1;" : "=r"(u) : "f"(f));
    return u;
}
__device__ __forceinline__ void mma_tf32(float* c, const unsigned* a, const unsigned* b) {
    asm volatile(
        "mma.sync.aligned.m16n8k8.row.col.f32.tf32.tf32.f32 "
        "{%0,%1,%2,%3},{%4,%5,%6,%7},{%8,%9},{%0,%1,%2,%3};"
        : "+f"(c[0]), "+f"(c[1]), "+f"(c[2]), "+f"(c[3])
        : "r"(a[0]), "r"(a[1]), "r"(a[2]), "r"(a[3]), "r"(b[0]), "r"(b[1]));
}

// fp8 e4m3 pack: returns (fp8(hi)<<8)|fp8(lo)
__device__ __forceinline__ unsigned short f2_to_fp8x2(float hi, float lo) {
    unsigned short r;
    asm("cvt.rn.satfinite.e4m3x2.f32 %0, %1, %2;" : "=h"(r) : "f"(hi), "f"(lo));
    return r;
}
// fp8x2 (low 16 bits) -> half2
__device__ __forceinline__ __half2 fp8x2_to_h2(unsigned v) {
    unsigned r;
    unsigned short s = (unsigned short)v;
    asm("cvt.rn.f16x2.e4m3x2 %0, %1;" : "=r"(r) : "h"(s));
    return *(__half2*)&r;
}

__global__ void detect_all(const unsigned* __restrict__ ei, const unsigned* __restrict__ m) {
    int lane = threadIdx.x;
    int f32 = 0, multi = 0;
    for (int i = lane; i < 2048; i += 32) {
        unsigned w = m[i];
        if (w == 0x3F800000u) f32 = 1;
        else if (w > 1u) multi = 1;
    }
    f32 = __any_sync(0xffffffffu, f32);
    multi = __any_sync(0xffffffffu, multi);
    if (lane == 0) {
        g_maskmode = f32 ? 2 : (multi ? 0 : 1);
        unsigned o = ei[1] | ei[3] | ei[5] | ei[7] | ei[9] | ei[11] | ei[13] | ei[15];
        g_ei64 = (o == 0u) ? 1 : 0;
    }
}

// ---------------- CSR construction (self-loops pre-seeded: cnt starts at 1) ----------------
__global__ void init_cnt() {
    int i = blockIdx.x * blockDim.x + threadIdx.x;
    if (i < NN) g_cnt[i] = 1;
}
// vectorized: 4 edges per thread over NE real edges
__global__ void hist_kernel(const int* __restrict__ ei) {
    int e4 = (blockIdx.x * blockDim.x + threadIdx.x) * 4;
    if (e4 >= NE) return;
    int d0, d1, d2, d3;
    if (g_ei64) {
        int4 a = *(const int4*)&ei[2 * (NE + e4)];
        int4 b = *(const int4*)&ei[2 * (NE + e4) + 4];
        d0 = a.x; d1 = a.z; d2 = b.x; d3 = b.z;
    } else {
        int4 d = *(const int4*)&ei[NE + e4];
        d0 = d.x; d1 = d.y; d2 = d.z; d3 = d.w;
    }
    atomicAdd(&g_cnt[d0], 1);
    atomicAdd(&g_cnt[d1], 1);
    atomicAdd(&g_cnt[d2], 1);
    atomicAdd(&g_cnt[d3], 1);
}
__global__ void scan1() {
    __shared__ int sh[256];
    int t = threadIdx.x;
    int i = blockIdx.x * 256 + t;
    int v = (i < NN) ? g_cnt[i] : 0;
    sh[t] = v;
    __syncthreads();
#pragma unroll
    for (int off = 1; off < 256; off <<= 1) {
        int add = (t >= off) ? sh[t - off] : 0;
        __syncthreads();
        sh[t] += add;
        __syncthreads();
    }
    if (i < NN) g_off[i] = sh[t] - v;
    if (t == 255) g_bsum[blockIdx.x] = sh[255];
}
__global__ void scan2() {
    __shared__ int sh[256];
    int t = threadIdx.x;
    int v = (t < NB_SCAN) ? g_bsum[t] : 0;
    sh[t] = v;
    __syncthreads();
#pragma unroll
    for (int off = 1; off < 256; off <<= 1) {
        int add = (t >= off) ? sh[t - off] : 0;
        __syncthreads();
        sh[t] += add;
        __syncthreads();
    }
    if (t < NB_SCAN) g_bsumoff[t] = sh[t] - v;
}
// finalize offsets + place self-loop entry
__global__ void scan3() {
    int i = blockIdx.x * blockDim.x + threadIdx.x;
    if (i >= NN) return;
    int o = g_off[i] + g_bsumoff[i >> 8];
    g_off[i] = o;
    g_csrc[o] = i;        // self-loop source
    g_woff[i] = o + 1;    // real edges fill after it
}
// vectorized: 4 edges per thread
__global__ void fill_kernel(const int* __restrict__ ei) {
    int e4 = (blockIdx.x * blockDim.x + threadIdx.x) * 4;
    if (e4 >= NE) return;
    int s0, s1, s2, s3, d0, d1, d2, d3;
    if (g_ei64) {
        int4 a = *(const int4*)&ei[2 * e4];
        int4 b = *(const int4*)&ei[2 * e4 + 4];
        s0 = a.x; s1 = a.z; s2 = b.x; s3 = b.z;
        int4 c = *(const int4*)&ei[2 * (NE + e4)];
        int4 e = *(const int4*)&ei[2 * (NE + e4) + 4];
        d0 = c.x; d1 = c.z; d2 = e.x; d3 = e.z;
    } else {
        int4 s = *(const int4*)&ei[e4];
        int4 d = *(const int4*)&ei[NE + e4];
        s0 = s.x; s1 = s.y; s2 = s.z; s3 = s.w;
        d0 = d.x; d1 = d.y; d2 = d.z; d3 = d.w;
    }
    g_csrc[atomicAdd(&g_woff[d0], 1)] = s0;
    g_csrc[atomicAdd(&g_woff[d1], 1)] = s1;
    g_csrc[atomicAdd(&g_woff[d2], 1)] = s2;
    g_csrc[atomicAdd(&g_woff[d3], 1)] = s3;
}

// ---------------- TF32 GEMM + fused attention-dot epilogue + fp8/bf16 store ----------------
template <int STORE_FP8>
__global__ void __launch_bounds__(256) gemm_att(const float* __restrict__ A,
                                                const float* __restrict__ B,
                                                void* __restrict__ Cout,
                                                const float* __restrict__ att_s,
                                                const float* __restrict__ att_d,
                                                float* __restrict__ as_out,
                                                float* __restrict__ ad_out,
                                                int S, int M, int N, int K) {
    const int BM = 128, BK = 16;
    __shared__ float As[BK][BM + 4];
    __shared__ float Bs[BK][64 + 4];
    __shared__ float sAttS[64], sAttD[64];
    __shared__ float sRedS[2][128], sRedD[2][128];
    int tid = threadIdx.x;
    int bx = blockIdx.x;
    int bm = blockIdx.y * BM, bn = bx * 64;
    int wid = tid >> 5, lane = tid & 31;
    int wm = wid & 3, wn = wid >> 2;
    int g = lane >> 2, t = lane & 3;

    if (tid < 64) sAttS[tid] = att_s[bx * 64 + tid];
    else if (tid < 128) sAttD[tid - 64] = att_d[bx * 64 + tid - 64];

    float acc[2][4][4];
#pragma unroll
    for (int mf = 0; mf < 2; mf++)
#pragma unroll
        for (int nf = 0; nf < 4; nf++)
#pragma unroll
            for (int i = 0; i < 4; i++) acc[mf][nf][i] = 0.f;

    for (int k0 = 0; k0 < K; k0 += BK) {
#pragma unroll
        for (int i = 0; i < 2; i++) {
            int row = (tid >> 2) + i * 64;
            int c4 = (tid & 3) * 4;
            float4 v = make_float4(0.f, 0.f, 0.f, 0.f);
            if (bm + row < M)
                v = *(const float4*)&A[(size_t)(bm + row) * K + k0 + c4];
            As[c4 + 0][row] = v.x;
            As[c4 + 1][row] = v.y;
            As[c4 + 2][row] = v.z;
            As[c4 + 3][row] = v.w;
        }
        {
            int bRow = tid >> 4, bCol = (tid & 15) * 4;
            *(float4*)&Bs[bRow][bCol] = *(const float4*)&B[(size_t)(k0 + bRow) * N + bn + bCol];
        }
        __syncthreads();
#pragma unroll
        for (int k2 = 0; k2 < 2; k2++) {
            int kk = k2 * 8;
            unsigned aF[2][4], bF[4][2];
#pragma unroll
            for (int mf = 0; mf < 2; mf++) {
                int m0 = wm * 32 + mf * 16 + g;
                aF[mf][0] = f2tf(As[kk + t][m0]);
                aF[mf][1] = f2tf(As[kk + t][m0 + 8]);
                aF[mf][2] = f2tf(As[kk + t + 4][m0]);
                aF[mf][3] = f2tf(As[kk + t + 4][m0 + 8]);
            }
#pragma unroll
            for (int nf = 0; nf < 4; nf++) {
                int n0 = wn * 32 + nf * 8 + g;
                bF[nf][0] = f2tf(Bs[kk + t][n0]);
                bF[nf][1] = f2tf(Bs[kk + t + 4][n0]);
            }
#pragma unroll
            for (int mf = 0; mf < 2; mf++)
#pragma unroll
                for (int nf = 0; nf < 4; nf++)
                    mma_tf32(acc[mf][nf], aF[mf], bF[nf]);
        }
        __syncthreads();
    }

    float psS[2][2] = {{0.f, 0.f}, {0.f, 0.f}};
    float psD[2][2] = {{0.f, 0.f}, {0.f, 0.f}};
#pragma unroll
    for (int mf = 0; mf < 2; mf++) {
#pragma unroll
        for (int nf = 0; nf < 4; nf++) {
            int colL = wn * 32 + nf * 8 + 2 * t;
            float aS0 = sAttS[colL], aS1 = sAttS[colL + 1];
            float aD0 = sAttD[colL], aD1 = sAttD[colL + 1];
            float* c = acc[mf][nf];
            psS[mf][0] += c[0] * aS0 + c[1] * aS1;
            psS[mf][1] += c[2] * aS0 + c[3] * aS1;
            psD[mf][0] += c[0] * aD0 + c[1] * aD1;
            psD[mf][1] += c[2] * aD0 + c[3] * aD1;
            int r = bm + wm * 32 + mf * 16 + g;
            if (STORE_FP8) {
                unsigned char* Cf8 = (unsigned char*)Cout;
                unsigned short p0 = f2_to_fp8x2(c[1], c[0]);
                unsigned short p1 = f2_to_fp8x2(c[3], c[2]);
                if (r < M)     *(unsigned short*)&Cf8[(size_t)r * N + bn + colL] = p0;
                if (r + 8 < M) *(unsigned short*)&Cf8[(size_t)(r + 8) * N + bn + colL] = p1;
            } else {
                __nv_bfloat16* Cbf = (__nv_bfloat16*)Cout;
                __nv_bfloat162 p0 = __floats2bfloat162_rn(c[0], c[1]);
                __nv_bfloat162 p1 = __floats2bfloat162_rn(c[2], c[3]);
                if (r < M)     *(__nv_bfloat162*)&Cbf[(size_t)r * N + bn + colL] = p0;
                if (r + 8 < M) *(__nv_bfloat162*)&Cbf[(size_t)(r + 8) * N + bn + colL] = p1;
            }
        }
    }
#pragma unroll
    for (int mf = 0; mf < 2; mf++)
#pragma unroll
        for (int ro = 0; ro < 2; ro++) {
            psS[mf][ro] += __shfl_xor_sync(0xffffffffu, psS[mf][ro], 1);
            psS[mf][ro] += __shfl_xor_sync(0xffffffffu, psS[mf][ro], 2);
            psD[mf][ro] += __shfl_xor_sync(0xffffffffu, psD[mf][ro], 1);
            psD[mf][ro] += __shfl_xor_sync(0xffffffffu, psD[mf][ro], 2);
        }
    if (t == 0) {
#pragma unroll
        for (int mf = 0; mf < 2; mf++)
#pragma unroll
            for (int ro = 0; ro < 2; ro++) {
                int rl = wm * 32 + mf * 16 + ro * 8 + g;
                sRedS[wn][rl] = psS[mf][ro];
                sRedD[wn][rl] = psD[mf][ro];
            }
    }
    __syncthreads();
    if (tid < 128 && bm + tid < M) {
        as_out[(size_t)(bm + tid) * S + bx] = sRedS[0][tid] + sRedS[1][tid];
        ad_out[(size_t)(bm + tid) * S + bx] = sRedD[0][tid] + sRedD[1][tid];
    }
}

// accumulate one fp8 row (16 features in uint4) into 8 half2 accs
// NOTE: parameter names must not collide with struct members (.x/.y/.z/.w)
#define ACC1(rr, cf)                                             \
    do {                                                         \
        acc[0] = __hfma2(cf, fp8x2_to_h2((rr).x), acc[0]);       \
        acc[1] = __hfma2(cf, fp8x2_to_h2((rr).x >> 16), acc[1]); \
        acc[2] = __hfma2(cf, fp8x2_to_h2((rr).y), acc[2]);       \
        acc[3] = __hfma2(cf, fp8x2_to_h2((rr).y >> 16), acc[3]); \
        acc[4] = __hfma2(cf, fp8x2_to_h2((rr).z), acc[4]);       \
        acc[5] = __hfma2(cf, fp8x2_to_h2((rr).z >> 16), acc[5]); \
        acc[6] = __hfma2(cf, fp8x2_to_h2((rr).w), acc[6]);       \
        acc[7] = __hfma2(cf, fp8x2_to_h2((rr).w >> 16), acc[7]); \
    } while (0)

// ---------------- layer 1 gather: warp per dst node, 2 edges/iter via half-warps ----------------
__global__ void __launch_bounds__(256) node1_kernel(const float* __restrict__ b1) {
    __shared__ float s_ex[8][CAP * 4];
    __shared__ int   s_src[8][CAP];
    int w = (blockIdx.x * blockDim.x + threadIdx.x) >> 5;
    int lane = threadIdx.x & 31;
    int wl = threadIdx.x >> 5;
    if (w >= NN) return;
    int base = g_off[w];
    int deg  = g_cnt[w];
    float4 ad = *(const float4*)(g_ad1 + (size_t)w * 4);

    // pass A: ex = exp(lrelu(as+ad)) per head; cache; denominator
    float4 den = make_float4(0.f, 0.f, 0.f, 0.f);
    for (int j = lane; j < deg; j += 32) {
        int s = g_csrc[base + j];
        float4 as = *(const float4*)(g_as1 + (size_t)s * 4);
        float4 ex;
        ex.x = __expf(lrelu(as.x + ad.x));
        ex.y = __expf(lrelu(as.y + ad.y));
        ex.z = __expf(lrelu(as.z + ad.z));
        ex.w = __expf(lrelu(as.w + ad.w));
        if (j < CAP) {
            s_src[wl][j] = s;
            *(float4*)&s_ex[wl][j * 4] = ex;
        }
        den.x += ex.x; den.y += ex.y; den.z += ex.z; den.w += ex.w;
    }
    den.x = warp_sum(den.x); den.y = warp_sum(den.y);
    den.z = warp_sum(den.z); den.w = warp_sum(den.w);
    __syncwarp();

    // pass B: half-warp per edge; 16 lanes x 16B = full 256B row
    int half = lane >> 4;
    int hl   = lane & 15;
    int head = hl >> 2;
    float adh = head == 0 ? ad.x : head == 1 ? ad.y : head == 2 ? ad.z : ad.w;
    float dh  = head == 0 ? den.x : head == 1 ? den.y : head == 2 ? den.z : den.w;
    __half2 hz = __float2half2_rn(0.f);
    __half2 acc[8];
#pragma unroll
    for (int k = 0; k < 8; k++) acc[k] = hz;

    const unsigned char* rowbase = g_h1f8 + hl * 16;

    if (deg <= CAP) {
        int j = half;
        for (; j + 6 < deg; j += 8) {
            int s0 = s_src[wl][j];
            int s1 = s_src[wl][j + 2];
            int s2 = s_src[wl][j + 4];
            int s3 = s_src[wl][j + 6];
            float e0 = s_ex[wl][j * 4 + head];
            float e1 = s_ex[wl][(j + 2) * 4 + head];
            float e2 = s_ex[wl][(j + 4) * 4 + head];
            float e3 = s_ex[wl][(j + 6) * 4 + head];
            uint4 r0 = *(const uint4*)(rowbase + (size_t)s0 * HC);
            uint4 r1 = *(const uint4*)(rowbase + (size_t)s1 * HC);
            uint4 r2 = *(const uint4*)(rowbase + (size_t)s2 * HC);
            uint4 r3 = *(const uint4*)(rowbase + (size_t)s3 * HC);
            __half2 c0 = __float2half2_rn(e0);
            __half2 c1 = __float2half2_rn(e1);
            __half2 c2 = __float2half2_rn(e2);
            __half2 c3 = __float2half2_rn(e3);
            ACC1(r0, c0);
            ACC1(r1, c1);
            ACC1(r2, c2);
            ACC1(r3, c3);
        }
        for (; j < deg; j += 2) {
            int s = s_src[wl][j];
            float e = s_ex[wl][j * 4 + head];
            uint4 r = *(const uint4*)(rowbase + (size_t)s * HC);
            __half2 c = __float2half2_rn(e);
            ACC1(r, c);
        }
    } else {
        for (int j = half; j < deg; j += 2) {
            int s; float e;
            if (j < CAP) {
                s = s_src[wl][j];
                e = s_ex[wl][j * 4 + head];
            } else {
                s = g_csrc[base + j];
                e = __expf(lrelu(g_as1[(size_t)s * 4 + head] + adh));
            }
            uint4 r = *(const uint4*)(rowbase + (size_t)s * HC);
            __half2 c = __float2half2_rn(e);
            ACC1(r, c);
        }
    }

    // combine halves (lanes l and l+16 hold same features, disjoint edges)
#pragma unroll
    for (int k = 0; k < 8; k++) {
        unsigned u = *(unsigned*)&acc[k];
        u = __shfl_xor_sync(0xffffffffu, u, 16);
        acc[k] = __hadd2(acc[k], *(__half2*)&u);
    }

    if (half == 0) {
        float inv = 1.f / dh;
        int f = hl * 16;
        float* op = g_h1 + (size_t)w * HC + f;
        const float4* bp = (const float4*)(b1 + f);
#pragma unroll
        for (int k = 0; k < 4; k++) {
            float2 lo = __half22float2(acc[2 * k]);
            float2 hi = __half22float2(acc[2 * k + 1]);
            float4 bb = bp[k];
            float4 o;
            o.x = fmaxf(lo.x * inv + bb.x, 0.f);
            o.y = fmaxf(lo.y * inv + bb.y, 0.f);
            o.z = fmaxf(hi.x * inv + bb.z, 0.f);
            o.w = fmaxf(hi.y * inv + bb.w, 0.f);
            *(float4*)(op + k * 4) = o;
        }
    }
}

// ---------------- layer 2 gather + node scores: half-warp per edge ----------------
__global__ void __launch_bounds__(256) node2_kernel(const float* __restrict__ b2,
                                                    const float* __restrict__ aw,
                                                    const float* __restrict__ ab) {
    __shared__ float s_ex[8][CAP];
    __shared__ int   s_src[8][CAP];
    int w = (blockIdx.x * blockDim.x + threadIdx.x) >> 5;
    int lane = threadIdx.x & 31;
    int wl = threadIdx.x >> 5;
    if (w >= NN) return;
    int base = g_off[w];
    int deg  = g_cnt[w];
    float ad = g_ad2[w];

    float den = 0.f;
    for (int j = lane; j < deg; j += 32) {
        int s = g_csrc[base + j];
        float ex = __expf(lrelu(g_as2[s] + ad));
        if (j < CAP) { s_src[wl][j] = s; s_ex[wl][j] = ex; }
        den += ex;
    }
    den = warp_sum(den);
    __syncwarp();

    int half = lane >> 4;
    int hl   = lane & 15;
    float a0 = 0.f, a1 = 0.f, a2 = 0.f, a3 = 0.f;
    const __nv_bfloat16* rowbase = g_h2bf + hl * 4;

    if (deg <= CAP) {
        int j = half;
        for (; j + 6 < deg; j += 8) {
            int s0 = s_src[wl][j];
            int s1 = s_src[wl][j + 2];
            int s2 = s_src[wl][j + 4];
            int s3 = s_src[wl][j + 6];
            float e0 = s_ex[wl][j];
            float e1 = s_ex[wl][j + 2];
            float e2 = s_ex[wl][j + 4];
            float e3 = s_ex[wl][j + 6];
            uint2 v0 = *(const uint2*)(rowbase + (size_t)s0 * HID);
            uint2 v1 = *(const uint2*)(rowbase + (size_t)s1 * HID);
            uint2 v2 = *(const uint2*)(rowbase + (size_t)s2 * HID);
            uint2 v3 = *(const uint2*)(rowbase + (size_t)s3 * HID);
            float2 p0 = __bfloat1622float2(*(const __nv_bfloat162*)&v0.x);
            float2 q0 = __bfloat1622float2(*(const __nv_bfloat162*)&v0.y);
            float2 p1 = __bfloat1622float2(*(const __nv_bfloat162*)&v1.x);
            float2 q1 = __bfloat1622float2(*(const __nv_bfloat162*)&v1.y);
            float2 p2 = __bfloat1622float2(*(const __nv_bfloat162*)&v2.x);
            float2 q2 = __bfloat1622float2(*(const __nv_bfloat162*)&v2.y);
            float2 p3 = __bfloat1622float2(*(const __nv_bfloat162*)&v3.x);
            float2 q3 = __bfloat1622float2(*(const __nv_bfloat162*)&v3.y);
            a0 += e0 * p0.x + e1 * p1.x + e2 * p2.x + e3 * p3.x;
            a1 += e0 * p0.y + e1 * p1.y + e2 * p2.y + e3 * p3.y;
            a2 += e0 * q0.x + e1 * q1.x + e2 * q2.x + e3 * q3.x;
            a3 += e0 * q0.y + e1 * q1.y + e2 * q2.y + e3 * q3.y;
        }
        for (; j < deg; j += 2) {
            int s = s_src[wl][j];
            float e = s_ex[wl][j];
            uint2 v = *(const uint2*)(rowbase + (size_t)s * HID);
            float2 p = __bfloat1622float2(*(const __nv_bfloat162*)&v.x);
            float2 q = __bfloat1622float2(*(const __nv_bfloat162*)&v.y);
            a0 += e * p.x; a1 += e * p.y; a2 += e * q.x; a3 += e * q.y;
        }
    } else {
        for (int j = half; j < deg; j += 2) {
            int s; float e;
            if (j < CAP) { s = s_src[wl][j]; e = s_ex[wl][j]; }
            else {
                s = g_csrc[base + j];
                e = __expf(lrelu(g_as2[s] + ad));
            }
            uint2 v = *(const uint2*)(rowbase + (size_t)s * HID);
            float2 p = __bfloat1622float2(*(const __nv_bfloat162*)&v.x);
            float2 q = __bfloat1622float2(*(const __nv_bfloat162*)&v.y);
            a0 += e * p.x; a1 += e * p.y; a2 += e * q.x; a3 += e * q.y;
        }
    }

    // combine halves
    a0 += __shfl_xor_sync(0xffffffffu, a0, 16);
    a1 += __shfl_xor_sync(0xffffffffu, a1, 16);
    a2 += __shfl_xor_sync(0xffffffffu, a2, 16);
    a3 += __shfl_xor_sync(0xffffffffu, a3, 16);

    float inv = 1.f / den;
    int c = hl * 4;
    float h0 = a0 * inv + b2[c];
    float h1 = a1 * inv + b2[c + 1];
    float h2 = a2 * inv + b2[c + 2];
    float h3 = a3 * inv + b2[c + 3];
    if (half == 0)
        *(float4*)(g_h2 + (size_t)w * HID + c) = make_float4(h0, h1, h2, h3);

    // score: both halves hold identical values -> reduce within 16-lane group
    float sc = h0 * aw[c] + h1 * aw[c + 1] + h2 * aw[c + 2] + h3 * aw[c + 3];
#pragma unroll
    for (int o = 8; o; o >>= 1) sc += __shfl_xor_sync(0xffffffffu, sc, o);
    if (lane == 0) g_scores[w] = tanhf(sc + ab[0]);
}

// ---------------- per-graph pooled stop score ----------------
__global__ void context_kernel(const int* __restrict__ cn, const int* __restrict__ cc,
                               const float* __restrict__ sw, const float* __restrict__ sb) {
    int g = blockIdx.x;
    int c = threadIdx.x;   // 64 threads
    int cnt = cc[g];
    float sum = 0.f;
#pragma unroll
    for (int k = 0; k < KMAX; k++) {
        if (k < cnt) {
            int n = cn[g * KMAX + k];
            sum += g_h2[(size_t)n * HID + c];
        }
    }
    int cm = cnt > 1 ? cnt : 1;
    float ctx = sum / (float)cm;
    __shared__ float red[64];
    red[c] = ctx * sw[c];
    __syncthreads();
    for (int o = 32; o; o >>= 1) {
        if (c < o) red[c] += red[c + o];
        __syncthreads();
    }
    if (c == 0) g_stop[g] = tanhf(red[0] + sb[0]);
}

__device__ __forceinline__ bool get_mask(const void* masks, int mode, int g, int i) {
    if (mode == 2) return ((const float*)masks)[(size_t)g * NN + i] != 0.f;
    if (mode == 1) return ((const int*)masks)[(size_t)g * NN + i] != 0;
    return ((const unsigned char*)masks)[(size_t)g * NN + i] != 0;
}

// ---------------- split softmax ----------------
__global__ void __launch_bounds__(256) softmaxA(const void* __restrict__ masks) {
    int g = blockIdx.x >> 3, ch = blockIdx.x & 7;
    int tid = threadIdx.x;
    int i0 = ch * CHUNK;
    int mode = g_maskmode;
    __shared__ float sm[8];

    float mx = -3.4e38f;
    for (int i = tid; i < CHUNK; i += 256) {
        int idx = i0 + i;
        float s = get_mask(masks, mode, g, idx) ? g_scores[idx] : -1e9f;
        mx = fmaxf(mx, s);
    }
    mx = warp_max(mx);
    if ((tid & 31) == 0) sm[tid >> 5] = mx;
    __syncthreads();
    if (tid < 32) {
        float v = (tid < 8) ? sm[tid] : -3.4e38f;
        v = warp_max(v);
        if (tid == 0) sm[0] = v;
    }
    __syncthreads();
    mx = sm[0];
    __syncthreads();

    float sum = 0.f;
    for (int i = tid; i < CHUNK; i += 256) {
        int idx = i0 + i;
        float s = get_mask(masks, mode, g, idx) ? g_scores[idx] : -1e9f;
        sum += __expf(s - mx);
    }
    sum = warp_sum(sum);
    if ((tid & 31) == 0) sm[tid >> 5] = sum;
    __syncthreads();
    if (tid < 32) {
        float v = (tid < 8) ? sm[tid] : 0.f;
        v = warp_sum(v);
        if (tid == 0) {
            g_pm[g * SCH + ch] = mx;
            g_ps[g * SCH + ch] = v;
        }
    }
}

__global__ void softmaxB(const int* __restrict__ cc, float* __restrict__ out) {
    int g = blockIdx.x;
    int lane = threadIdx.x;
    float m = (lane < SCH) ? g_pm[g * SCH + lane] : -3.4e38f;
    float M = warp_max(m);
    float stop = g_stop[g];
    M = fmaxf(M, stop);
    float s = (lane < SCH) ? g_ps[g * SCH + lane] * __expf(m - M) : 0.f;
    float Ssum = warp_sum(s) + __expf(stop - M);
    if (lane == 0) {
        g_smx[g] = M;
        float inv = 1.f / Ssum;
        g_sinv[g] = inv;
        out[(size_t)g * NP1 + NN] = (cc[g] == 0) ? 1.f : __expf(stop - M) * inv;
    }
}

__global__ void __launch_bounds__(256) softmaxC(const void* __restrict__ masks,
                                                const int* __restrict__ cc,
                                                float* __restrict__ out) {
    int g = blockIdx.x >> 3, ch = blockIdx.x & 7;
    int tid = threadIdx.x;
    int i0 = ch * CHUNK;
    int mode = g_maskmode;
    float* o = out + (size_t)g * NP1;
    if (cc[g] == 0) {
        for (int i = tid; i < CHUNK; i += 256) o[i0 + i] = 0.f;
        return;
    }
    float mx = g_smx[g], inv = g_sinv[g];
    for (int i = tid; i < CHUNK; i += 256) {
        int idx = i0 + i;
        float s = get_mask(masks, mode, g, idx) ? g_scores[idx] : -1e9f;
        o[idx] = __expf(s - mx) * inv;
    }
}

// ---------------- host ----------------
extern "C" void kernel_launch(void* const* d_in, const int* in_sizes, int n_in,
                              void* d_out, int out_size) {
    const float* x    = (const float*)d_in[0];
    const int*   ei   = (const int*)d_in[1];
    const int*   cn   = (const int*)d_in[2];
    const int*   cc   = (const int*)d_in[3];
    const void*  masks = d_in[4];
    const float* W1   = (const float*)d_in[5];
    const float* as1w = (const float*)d_in[6];
    const float* ad1w = (const float*)d_in[7];
    const float* b1   = (const float*)d_in[8];
    const float* W2   = (const float*)d_in[9];
    const float* as2w = (const float*)d_in[10];
    const float* ad2w = (const float*)d_in[11];
    const float* b2   = (const float*)d_in[12];
    const float* aw   = (const float*)d_in[13];
    const float* ab   = (const float*)d_in[14];
    const float* sw   = (const float*)d_in[15];
    const float* sb   = (const float*)d_in[16];
    float* out = (float*)d_out;

    unsigned char* h1f8_p;
    __nv_bfloat16* h2bf_p;
    float *h1_p, *as1_p, *ad1_p, *as2_p, *ad2_p;
    cudaGetSymbolAddress((void**)&h1f8_p, g_h1f8);
    cudaGetSymbolAddress((void**)&h1_p, g_h1);
    cudaGetSymbolAddress((void**)&h2bf_p, g_h2bf);
    cudaGetSymbolAddress((void**)&as1_p, g_as1);
    cudaGetSymbolAddress((void**)&ad1_p, g_ad1);
    cudaGetSymbolAddress((void**)&as2_p, g_as2);
    cudaGetSymbolAddress((void**)&ad2_p, g_ad2);

    static cudaStream_t s2 = nullptr;
    static cudaEvent_t evFork = nullptr, evJoin = nullptr, evN2 = nullptr, evCtx = nullptr;
    if (!s2) {
        cudaStreamCreateWithFlags(&s2, cudaStreamNonBlocking);
        cudaEventCreateWithFlags(&evFork, cudaEventDisableTiming);
        cudaEventCreateWithFlags(&evJoin, cudaEventDisableTiming);
        cudaEventCreateWithFlags(&evN2, cudaEventDisableTiming);
        cudaEventCreateWithFlags(&evCtx, cudaEventDisableTiming);
    }

    // fork: detect + CSR build on s2; GEMM1 (independent) on main
    cudaEventRecord(evFork, 0);
    cudaStreamWaitEvent(s2, evFork, 0);
    detect_all<<<1, 32, 0, s2>>>((const unsigned*)ei, (const unsigned*)masks);
    init_cnt<<<(NN + 255) / 256, 256, 0, s2>>>();
    hist_kernel<<<(NE / 4 + 255) / 256, 256, 0, s2>>>(ei);
    scan1<<<NB_SCAN, 256, 0, s2>>>();
    scan2<<<1, 256, 0, s2>>>();
    scan3<<<NB_SCAN, 256, 0, s2>>>();
    fill_kernel<<<(NE / 4 + 255) / 256, 256, 0, s2>>>(ei);
    cudaEventRecord(evJoin, s2);

    // layer 1 GEMM (+att dots + fp8 store fused)
    gemm_att<1><<<dim3(HEADS, (NN + 127) / 128), 256>>>(x, W1, h1f8_p, as1w, ad1w,
                                                        as1_p, ad1_p, HEADS, NN, HC, FIN);
    cudaStreamWaitEvent(0, evJoin, 0);
    node1_kernel<<<(NN + 7) / 8, 256>>>(b1);

    // layer 2
    gemm_att<0><<<dim3(1, (NN + 127) / 128), 256>>>(h1_p, W2, h2bf_p, as2w, ad2w,
                                                    as2_p, ad2_p, 1, NN, HID, HC);
    node2_kernel<<<(NN + 7) / 8, 256>>>(b2, aw, ab);

    // heads: context on s2 overlaps softmaxA on main
    cudaEventRecord(evN2, 0);
    cudaStreamWaitEvent(s2, evN2, 0);
    context_kernel<<<NG, 64, 0, s2>>>(cn, cc, sw, sb);
    cudaEventRecord(evCtx, s2);
    softmaxA<<<NG * SCH, 256>>>(masks);
    cudaStreamWaitEvent(0, evCtx, 0);
    softmaxB<<<NG, 32>>>(cc, out);
    softmaxC<<<NG * SCH, 256>>>(masks, cc, out);
}